// round 1
// baseline (speedup 1.0000x reference)
#include <cuda_runtime.h>
#include <cstddef>

// ---------------- problem constants ----------------
#define BATCH   4
#define NV      4096
#define NL      256
#define EMBED   1024
#define HEADS   16
#define HDIM    64
#define LDIM    768
#define BH      (BATCH*HEADS)          // 64
#define MV      (BATCH*NV)             // 16384
#define ML      (BATCH*NL)             // 1024

// ---------------- scratch (device globals; no allocs allowed) ----------------
__device__ float g_q   [(size_t)MV*EMBED];   // 64 MB  vision queries
__device__ float g_valv[(size_t)MV*EMBED];   // 64 MB  vision values
__device__ float g_k   [(size_t)ML*EMBED];   // 4 MB   language keys
__device__ float g_vall[(size_t)ML*EMBED];   // 4 MB   language values
__device__ float g_S   [(size_t)BH*NV*NL];   // 256 MB raw scores (unmasked, scaled)
__device__ float g_ov  [(size_t)MV*EMBED];   // 64 MB  out_v heads
__device__ float g_ol  [(size_t)ML*EMBED];   // 4 MB   out_l heads
__device__ float g_colm[BH*NL];
__device__ float g_cols[BH*NL];

// ---------------- generic SGEMM: C[M,N] = A[M,K] @ B[K,N] + bias[N] ----------------
// 128x128 tile, BK=8, 256 threads, 8x8 per thread, float4 everywhere.
// Requires M%128==0, N%128==0, K%8==0 (holds for all six calls).
__global__ __launch_bounds__(256) void sgemm_bias(
    const float* __restrict__ A, const float* __restrict__ B,
    const float* __restrict__ bias, float* __restrict__ C,
    int M, int N, int K)
{
    __shared__ float As[8][128];
    __shared__ float Bs[8][128];
    const int tid  = threadIdx.x;
    const int tx   = tid & 15;
    const int ty   = tid >> 4;
    const int crow = ty * 8;
    const int ccol = tx * 8;
    const int arow = tid >> 1;
    const int acol = (tid & 1) << 2;
    const int brow = tid >> 5;
    const int bcol = (tid & 31) << 2;

    const float* Ag = A + (size_t)(blockIdx.y * 128 + arow) * K + acol;
    const float* Bg = B + (size_t)brow * N + blockIdx.x * 128 + bcol;

    float acc[8][8];
    #pragma unroll
    for (int i = 0; i < 8; i++)
        #pragma unroll
        for (int j = 0; j < 8; j++) acc[i][j] = 0.f;

    for (int k0 = 0; k0 < K; k0 += 8) {
        float4 a4 = *(const float4*)(Ag + k0);
        As[acol + 0][arow] = a4.x;
        As[acol + 1][arow] = a4.y;
        As[acol + 2][arow] = a4.z;
        As[acol + 3][arow] = a4.w;
        *(float4*)&Bs[brow][bcol] = *(const float4*)(Bg + (size_t)k0 * N);
        __syncthreads();
        #pragma unroll
        for (int kk = 0; kk < 8; kk++) {
            float ra[8], rb[8];
            *(float4*)&ra[0] = *(const float4*)&As[kk][crow];
            *(float4*)&ra[4] = *(const float4*)&As[kk][crow + 4];
            *(float4*)&rb[0] = *(const float4*)&Bs[kk][ccol];
            *(float4*)&rb[4] = *(const float4*)&Bs[kk][ccol + 4];
            #pragma unroll
            for (int i = 0; i < 8; i++)
                #pragma unroll
                for (int j = 0; j < 8; j++)
                    acc[i][j] += ra[i] * rb[j];
        }
        __syncthreads();
    }

    float bb[8];
    #pragma unroll
    for (int j = 0; j < 8; j++) bb[j] = bias[blockIdx.x * 128 + ccol + j];
    #pragma unroll
    for (int i = 0; i < 8; i++) {
        float* Cp = C + (size_t)(blockIdx.y * 128 + crow + i) * N + blockIdx.x * 128 + ccol;
        float4 o0 = { acc[i][0] + bb[0], acc[i][1] + bb[1], acc[i][2] + bb[2], acc[i][3] + bb[3] };
        float4 o1 = { acc[i][4] + bb[4], acc[i][5] + bb[5], acc[i][6] + bb[6], acc[i][7] + bb[7] };
        *(float4*)Cp       = o0;
        *(float4*)(Cp + 4) = o1;
    }
}

// ---------------- scores: S[bh][q][k] = 0.25 * dot_d(q, k)  (UNMASKED) ----------------
// block: 128 q-rows x 64 k-cols, K-dim 64 in two 32-chunks. 256 threads, 8x4/thread.
__global__ __launch_bounds__(256) void scores_kernel()
{
    __shared__ float Qs[128][32];
    __shared__ float Ks[32][68];   // transposed [d][kcol], padded
    const int bh = blockIdx.z;
    const int b  = bh >> 4;
    const int h  = bh & 15;
    const int tid = threadIdx.x;
    const int tx = tid & 15;
    const int ty = tid >> 4;
    const int q0  = blockIdx.y * 128;
    const int kb0 = blockIdx.x * 64;

    float acc[8][4];
    #pragma unroll
    for (int i = 0; i < 8; i++)
        #pragma unroll
        for (int j = 0; j < 4; j++) acc[i][j] = 0.f;

    for (int k0 = 0; k0 < HDIM; k0 += 32) {
        #pragma unroll
        for (int i = 0; i < 4; i++) {
            int lin4 = i * 256 + tid;
            int qr = lin4 >> 3;
            int d4 = (lin4 & 7) << 2;
            *(float4*)&Qs[qr][d4] =
                *(const float4*)&g_q[((size_t)(b * NV + q0 + qr)) * EMBED + h * HDIM + k0 + d4];
        }
        #pragma unroll
        for (int i = 0; i < 2; i++) {
            int lin4 = i * 256 + tid;
            int kc = lin4 >> 3;
            int d4 = (lin4 & 7) << 2;
            float4 a = *(const float4*)&g_k[((size_t)(b * NL + kb0 + kc)) * EMBED + h * HDIM + k0 + d4];
            Ks[d4 + 0][kc] = a.x;
            Ks[d4 + 1][kc] = a.y;
            Ks[d4 + 2][kc] = a.z;
            Ks[d4 + 3][kc] = a.w;
        }
        __syncthreads();
        #pragma unroll
        for (int kd = 0; kd < 32; kd++) {
            float4 b4 = *(const float4*)&Ks[kd][tx * 4];
            #pragma unroll
            for (int i = 0; i < 8; i++) {
                float ra = Qs[ty * 8 + i][kd];
                acc[i][0] += ra * b4.x;
                acc[i][1] += ra * b4.y;
                acc[i][2] += ra * b4.z;
                acc[i][3] += ra * b4.w;
            }
        }
        __syncthreads();
    }
    #pragma unroll
    for (int i = 0; i < 8; i++) {
        float4 o = { acc[i][0] * 0.25f, acc[i][1] * 0.25f, acc[i][2] * 0.25f, acc[i][3] * 0.25f };
        *(float4*)&g_S[((size_t)bh * NV + q0 + ty * 8 + i) * NL + kb0 + tx * 4] = o;
    }
}

// ---------------- colstats: per (bh, k) online max/sumexp over q (language softmax, UNMASKED) ----------------
__global__ __launch_bounds__(1024) void colstats_kernel()
{
    __shared__ float sm[1024];
    __shared__ float ss[1024];
    const int bh  = blockIdx.x;
    const int tid = threadIdx.x;
    const int kk  = tid & 255;
    const int sub = tid >> 8;   // 0..3
    const float* Sb = g_S + (size_t)bh * NV * NL;

    float m = -3.0e38f, s = 0.f;
    for (int q = sub; q < NV; q += 4) {
        float x = Sb[(size_t)q * NL + kk];
        if (x > m) { s = s * __expf(m - x) + 1.f; m = x; }
        else       { s += __expf(x - m); }
    }
    sm[tid] = m; ss[tid] = s;
    __syncthreads();
    if (sub == 0) {
        float M0 = m, S0 = s;
        #pragma unroll
        for (int j = 1; j < 4; j++) {
            float m2 = sm[j * 256 + kk], s2 = ss[j * 256 + kk];
            float mm = fmaxf(M0, m2);
            S0 = S0 * __expf(M0 - mm) + s2 * __expf(m2 - mm);
            M0 = mm;
        }
        g_colm[bh * NL + kk] = M0;
        g_cols[bh * NL + kk] = S0;
    }
}

// ---------------- out_v: row softmax over Nl (masked) fused with @ val_l ----------------
// block: one bh, 64 q rows; 8 warps x 8 rows each; val_l staged in smem in 2 halves.
__global__ __launch_bounds__(256) void out_v_kernel(const int* __restrict__ mask)
{
    __shared__ float Vs[128][64];
    __shared__ float Ps[8][128];
    __shared__ float mb[256];
    const int bh = blockIdx.y;
    const int b  = bh >> 4;
    const int h  = bh & 15;
    const int tid  = threadIdx.x;
    const int w    = tid >> 5;
    const int lane = tid & 31;

    mb[tid] = (mask[b * NL + tid] == 0) ? -1.0e9f : 0.0f;
    __syncthreads();

    const float* Sbase = g_S + ((size_t)bh * NV + blockIdx.x * 64) * NL;

    float rm[8], ris[8];
    #pragma unroll
    for (int r = 0; r < 8; r++) {
        const float* Sr = Sbase + (size_t)(w * 8 + r) * NL;
        float sv[8], m = -3.0e38f;
        #pragma unroll
        for (int j = 0; j < 8; j++) {
            float x = Sr[lane + 32 * j] + mb[lane + 32 * j];
            sv[j] = x;
            m = fmaxf(m, x);
        }
        #pragma unroll
        for (int o = 16; o > 0; o >>= 1) m = fmaxf(m, __shfl_xor_sync(0xffffffffu, m, o));
        float s = 0.f;
        #pragma unroll
        for (int j = 0; j < 8; j++) s += __expf(sv[j] - m);
        #pragma unroll
        for (int o = 16; o > 0; o >>= 1) s += __shfl_xor_sync(0xffffffffu, s, o);
        rm[r]  = m;
        ris[r] = 1.0f / s;
    }

    float a0[8], a1[8];
    #pragma unroll
    for (int r = 0; r < 8; r++) { a0[r] = 0.f; a1[r] = 0.f; }

    for (int half = 0; half < 2; half++) {
        __syncthreads();
        #pragma unroll
        for (int i = 0; i < 8; i++) {
            int row = i * 16 + (tid >> 4);
            int col = (tid & 15) * 4;
            *(float4*)&Vs[row][col] =
                *(const float4*)&g_vall[((size_t)(b * NL + half * 128 + row)) * EMBED + h * HDIM + col];
        }
        __syncthreads();
        #pragma unroll
        for (int r = 0; r < 8; r++) {
            const float* Sr = Sbase + (size_t)(w * 8 + r) * NL + half * 128;
            #pragma unroll
            for (int j = 0; j < 4; j++) {
                int kk = lane + 32 * j;
                Ps[w][kk] = __expf(Sr[kk] + mb[half * 128 + kk] - rm[r]) * ris[r];
            }
            __syncwarp();
            #pragma unroll 8
            for (int kk = 0; kk < 128; kk++) {
                float pv = Ps[w][kk];
                a0[r] += pv * Vs[kk][lane];
                a1[r] += pv * Vs[kk][lane + 32];
            }
            __syncwarp();
        }
    }
    #pragma unroll
    for (int r = 0; r < 8; r++) {
        size_t base = ((size_t)(b * NV + blockIdx.x * 64 + w * 8 + r)) * EMBED + h * HDIM;
        g_ov[base + lane]      = a0[r];
        g_ov[base + 32 + lane] = a1[r];
    }
}

// ---------------- out_l: P^T @ val_v with exp on the fly (column softmax, UNMASKED) ----------------
// block: (ktile 64, bh). C tile 64k x 64d, 256 threads 4x4 each, q in chunks of 32.
__global__ __launch_bounds__(256) void out_l_kernel()
{
    __shared__ float Ps[32][64];
    __shared__ float Vs[32][64];
    __shared__ float ms[64];
    __shared__ float iss[64];
    const int bh = blockIdx.y;
    const int b  = bh >> 4;
    const int h  = bh & 15;
    const int kb0 = blockIdx.x * 64;
    const int tid = threadIdx.x;
    const int tx = tid & 15;
    const int ty = tid >> 4;

    if (tid < 64) {
        ms[tid]  = g_colm[bh * NL + kb0 + tid];
        iss[tid] = 1.0f / g_cols[bh * NL + kb0 + tid];
    }
    __syncthreads();

    float acc[4][4];
    #pragma unroll
    for (int i = 0; i < 4; i++)
        #pragma unroll
        for (int j = 0; j < 4; j++) acc[i][j] = 0.f;

    for (int qc = 0; qc < NV; qc += 32) {
        #pragma unroll
        for (int i = 0; i < 8; i++) {
            int lin = i * 256 + tid;
            int qq = lin >> 6;
            int cc = lin & 63;
            float x = g_S[((size_t)bh * NV + qc + qq) * NL + kb0 + cc];
            Ps[qq][cc] = __expf(x - ms[cc]) * iss[cc];
            Vs[qq][cc] = g_valv[((size_t)(b * NV + qc + qq)) * EMBED + h * HDIM + cc];
        }
        __syncthreads();
        #pragma unroll
        for (int qq = 0; qq < 32; qq++) {
            float4 pa = *(const float4*)&Ps[qq][ty * 4];
            float4 pb = *(const float4*)&Vs[qq][tx * 4];
            acc[0][0] += pa.x * pb.x; acc[0][1] += pa.x * pb.y; acc[0][2] += pa.x * pb.z; acc[0][3] += pa.x * pb.w;
            acc[1][0] += pa.y * pb.x; acc[1][1] += pa.y * pb.y; acc[1][2] += pa.y * pb.z; acc[1][3] += pa.y * pb.w;
            acc[2][0] += pa.z * pb.x; acc[2][1] += pa.z * pb.y; acc[2][2] += pa.z * pb.z; acc[2][3] += pa.z * pb.w;
            acc[3][0] += pa.w * pb.x; acc[3][1] += pa.w * pb.y; acc[3][2] += pa.w * pb.z; acc[3][3] += pa.w * pb.w;
        }
        __syncthreads();
    }
    #pragma unroll
    for (int i = 0; i < 4; i++) {
        float4 o = { acc[i][0], acc[i][1], acc[i][2], acc[i][3] };
        *(float4*)&g_ol[((size_t)(b * NL + kb0 + ty * 4 + i)) * EMBED + h * HDIM + tx * 4] = o;
    }
}

// ---------------- host launcher ----------------
extern "C" void kernel_launch(void* const* d_in, const int* in_sizes, int n_in,
                              void* d_out, int out_size)
{
    (void)in_sizes; (void)n_in; (void)out_size;
    const float* v       = (const float*)d_in[0];
    const float* l       = (const float*)d_in[1];
    const int*   mask    = (const int*)  d_in[2];
    const float* W_v2q   = (const float*)d_in[3];
    const float* b_v2q   = (const float*)d_in[4];
    const float* W_l2k   = (const float*)d_in[5];
    const float* b_l2k   = (const float*)d_in[6];
    const float* W_v2v   = (const float*)d_in[7];
    const float* b_v2v   = (const float*)d_in[8];
    const float* W_l2v   = (const float*)d_in[9];
    const float* b_l2v   = (const float*)d_in[10];
    const float* W_v2out = (const float*)d_in[11];
    const float* b_v2out = (const float*)d_in[12];
    const float* W_l2out = (const float*)d_in[13];
    const float* b_l2out = (const float*)d_in[14];
    float* out = (float*)d_out;

    float *p_q, *p_valv, *p_k, *p_vall, *p_ov, *p_ol;
    cudaGetSymbolAddress((void**)&p_q,    g_q);
    cudaGetSymbolAddress((void**)&p_valv, g_valv);
    cudaGetSymbolAddress((void**)&p_k,    g_k);
    cudaGetSymbolAddress((void**)&p_vall, g_vall);
    cudaGetSymbolAddress((void**)&p_ov,   g_ov);
    cudaGetSymbolAddress((void**)&p_ol,   g_ol);

    dim3 blk(256);

    // input projections
    sgemm_bias<<<dim3(EMBED / 128, MV / 128), blk>>>(v, W_v2q, b_v2q, p_q,    MV, EMBED, EMBED);
    sgemm_bias<<<dim3(EMBED / 128, MV / 128), blk>>>(v, W_v2v, b_v2v, p_valv, MV, EMBED, EMBED);
    sgemm_bias<<<dim3(EMBED / 128, ML / 128), blk>>>(l, W_l2k, b_l2k, p_k,    ML, EMBED, LDIM);
    sgemm_bias<<<dim3(EMBED / 128, ML / 128), blk>>>(l, W_l2v, b_l2v, p_vall, ML, EMBED, LDIM);

    // attention
    scores_kernel  <<<dim3(NL / 64, NV / 128, BH), blk>>>();
    colstats_kernel<<<dim3(BH), dim3(1024)>>>();
    out_v_kernel   <<<dim3(NV / 64, BH), blk>>>(mask);
    out_l_kernel   <<<dim3(NL / 64, BH), blk>>>();

    // output projections (written straight into d_out: out_v then out_l)
    sgemm_bias<<<dim3(EMBED / 128, MV / 128), blk>>>(p_ov, W_v2out, b_v2out, out, MV, EMBED, EMBED);
    sgemm_bias<<<dim3(LDIM / 128,  ML / 128), blk>>>(p_ol, W_l2out, b_l2out, out + (size_t)MV * EMBED, ML, LDIM, EMBED);
}

// round 3
// speedup vs baseline: 1.7449x; 1.7449x over previous
#include <cuda_runtime.h>
#include <cstdint>
#include <cstddef>

// ---------------- problem constants ----------------
#define BATCH   4
#define NV      4096
#define NL      256
#define EMBED   1024
#define HEADS   16
#define HDIM    64
#define LDIM    768
#define BH      (BATCH*HEADS)          // 64
#define MV      (BATCH*NV)             // 16384
#define ML      (BATCH*NL)             // 1024

// ---------------- scratch (device globals; no allocs allowed) ----------------
__device__ float g_q   [(size_t)MV*EMBED];   // 64 MB  vision queries
__device__ float g_valv[(size_t)MV*EMBED];   // 64 MB  vision values
__device__ float g_k   [(size_t)ML*EMBED];   // 4 MB   language keys
__device__ float g_vall[(size_t)ML*EMBED];   // 4 MB   language values
__device__ float g_S   [(size_t)BH*NV*NL];   // 256 MB raw scores (unmasked, scaled)
__device__ float g_ov  [(size_t)MV*EMBED];   // 64 MB  out_v heads
__device__ float g_ol  [(size_t)ML*EMBED];   // 4 MB   out_l heads
__device__ float g_colm[BH*NL];
__device__ float g_cols[BH*NL];
__device__ float g_Wt  [5505024];            // 21 MB transposed weights

// transposed-weight offsets (floats)
#define WT_V2Q   0
#define WT_L2K   1048576
#define WT_V2V   1835008
#define WT_L2V   2883584
#define WT_V2OUT 3670016
#define WT_L2OUT 4718592

// ---------------- weight transpose: Wt[n][k] = W[k][n] ----------------
__global__ void transpose_kn(const float* __restrict__ W, float* __restrict__ Wt, int K, int N)
{
    __shared__ float t[32][33];
    const int kb = blockIdx.y * 32, nb = blockIdx.x * 32;
    const int x = threadIdx.x, y = threadIdx.y;   // 32 x 8
    #pragma unroll
    for (int i = 0; i < 32; i += 8)
        t[y + i][x] = W[(size_t)(kb + y + i) * N + nb + x];
    __syncthreads();
    #pragma unroll
    for (int i = 0; i < 32; i += 8)
        Wt[(size_t)(nb + y + i) * K + kb + x] = t[x][y + i];
}

// ---------------- tf32 helpers ----------------
__device__ __forceinline__ float tf32_rn(float x) {
    uint32_t r;
    asm("cvt.rna.tf32.f32 %0, %1;" : "=r"(r) : "f"(x));
    return __uint_as_float(r);
}
__device__ __forceinline__ void mma_tf32(float* c, const uint32_t* a, const uint32_t* b) {
    asm volatile(
        "mma.sync.aligned.m16n8k8.row.col.f32.tf32.tf32.f32 "
        "{%0,%1,%2,%3}, {%4,%5,%6,%7}, {%8,%9}, {%0,%1,%2,%3};"
        : "+f"(c[0]), "+f"(c[1]), "+f"(c[2]), "+f"(c[3])
        : "r"(a[0]), "r"(a[1]), "r"(a[2]), "r"(a[3]), "r"(b[0]), "r"(b[1]));
}

// ---------------- tf32 mma.sync GEMM: C[M,N] = A[M,K] @ Bt[N,K]^T + bias[N] ----------------
// CTA 128x128, BK=32, 256 threads, 8 warps (2m x 4n), warp tile 64x32 = 4x4 m16n8k8.
// Double-buffered padded smem. Requires M%128==0, N%128==0, K%32==0.
#define ASTR   36                      // row stride in floats (+4 pad)
#define TBUF   (128*ASTR)              // 4608 floats per operand per stage

__global__ __launch_bounds__(256, 1) void mma_gemm(
    const float* __restrict__ A, const float* __restrict__ Bt,
    const float* __restrict__ bias, float* __restrict__ C,
    int M, int N, int K)
{
    extern __shared__ float smf[];
    float* As = smf;                   // [2][128][36]
    float* Bs = smf + 2 * TBUF;        // [2][128][36]
    __shared__ float sbias[128];

    const int tid  = threadIdx.x;
    const int w    = tid >> 5;
    const int lane = tid & 31;
    const int grp  = lane >> 2;
    const int tg   = lane & 3;
    const int wm   = (w & 1) * 64;
    const int wn   = (w >> 1) * 32;
    const int m0   = blockIdx.y * 128;
    const int n0   = blockIdx.x * 128;

    if (tid < 128) sbias[tid] = bias[n0 + tid];

    const float* Ab = A  + (size_t)m0 * K;
    const float* Bb = Bt + (size_t)n0 * K;
    const int ldr = tid >> 3;          // 0..31  (row block per 4-iter step)
    const int ldc = (tid & 7) * 4;     // 0..28

    float acc[4][4][4];
    #pragma unroll
    for (int i = 0; i < 4; i++)
        #pragma unroll
        for (int j = 0; j < 4; j++)
            #pragma unroll
            for (int t = 0; t < 4; t++) acc[i][j][t] = 0.f;

    const int NC = K / 32;

    // prologue: chunk 0 -> stage 0
    {
        #pragma unroll
        for (int i = 0; i < 4; i++) {
            int r = i * 32 + ldr;
            float4 va = *(const float4*)(Ab + (size_t)r * K + ldc);
            float4 vb = *(const float4*)(Bb + (size_t)r * K + ldc);
            float* da = As + r * ASTR + ldc;
            float* db = Bs + r * ASTR + ldc;
            da[0] = tf32_rn(va.x); da[1] = tf32_rn(va.y); da[2] = tf32_rn(va.z); da[3] = tf32_rn(va.w);
            db[0] = tf32_rn(vb.x); db[1] = tf32_rn(vb.y); db[2] = tf32_rn(vb.z); db[3] = tf32_rn(vb.w);
        }
    }
    __syncthreads();

    for (int c = 0; c < NC; c++) {
        const int b = c & 1;
        float4 pa[4], pb[4];
        if (c + 1 < NC) {
            const int k0 = (c + 1) * 32;
            #pragma unroll
            for (int i = 0; i < 4; i++) {
                int r = i * 32 + ldr;
                pa[i] = *(const float4*)(Ab + (size_t)r * K + k0 + ldc);
                pb[i] = *(const float4*)(Bb + (size_t)r * K + k0 + ldc);
            }
        }

        const float* Ac = As + b * TBUF;
        const float* Bc = Bs + b * TBUF;
        #pragma unroll
        for (int k0 = 0; k0 < 32; k0 += 8) {
            uint32_t af[4][4], bf[4][2];
            #pragma unroll
            for (int i = 0; i < 4; i++) {
                int row = wm + i * 16 + grp;
                af[i][0] = __float_as_uint(Ac[row * ASTR + k0 + tg]);
                af[i][1] = __float_as_uint(Ac[(row + 8) * ASTR + k0 + tg]);
                af[i][2] = __float_as_uint(Ac[row * ASTR + k0 + tg + 4]);
                af[i][3] = __float_as_uint(Ac[(row + 8) * ASTR + k0 + tg + 4]);
            }
            #pragma unroll
            for (int j = 0; j < 4; j++) {
                int n = wn + j * 8 + grp;
                bf[j][0] = __float_as_uint(Bc[n * ASTR + k0 + tg]);
                bf[j][1] = __float_as_uint(Bc[n * ASTR + k0 + tg + 4]);
            }
            #pragma unroll
            for (int i = 0; i < 4; i++)
                #pragma unroll
                for (int j = 0; j < 4; j++)
                    mma_tf32(acc[i][j], af[i], bf[j]);
        }

        if (c + 1 < NC) {
            __syncthreads();
            const int nb = 1 - b;
            float* da0 = As + nb * TBUF;
            float* db0 = Bs + nb * TBUF;
            #pragma unroll
            for (int i = 0; i < 4; i++) {
                int r = i * 32 + ldr;
                float* da = da0 + r * ASTR + ldc;
                float* db = db0 + r * ASTR + ldc;
                da[0] = tf32_rn(pa[i].x); da[1] = tf32_rn(pa[i].y); da[2] = tf32_rn(pa[i].z); da[3] = tf32_rn(pa[i].w);
                db[0] = tf32_rn(pb[i].x); db[1] = tf32_rn(pb[i].y); db[2] = tf32_rn(pb[i].z); db[3] = tf32_rn(pb[i].w);
            }
            __syncthreads();
        }
    }

    // epilogue
    #pragma unroll
    for (int i = 0; i < 4; i++) {
        int r0 = m0 + wm + i * 16 + grp;
        float* C0 = C + (size_t)r0 * N + n0;
        float* C1 = C + (size_t)(r0 + 8) * N + n0;
        #pragma unroll
        for (int j = 0; j < 4; j++) {
            int cc = wn + j * 8 + 2 * tg;
            float2 v0 = { acc[i][j][0] + sbias[cc], acc[i][j][1] + sbias[cc + 1] };
            float2 v1 = { acc[i][j][2] + sbias[cc], acc[i][j][3] + sbias[cc + 1] };
            *(float2*)(C0 + cc) = v0;
            *(float2*)(C1 + cc) = v1;
        }
    }
}
#define GEMM_SMEM (4 * TBUF * sizeof(float))   // 73728 bytes

// ---------------- scores: S[bh][q][k] = 0.25 * dot_d(q, k)  (UNMASKED) ----------------
__global__ __launch_bounds__(256) void scores_kernel()
{
    __shared__ float Qs[128][32];
    __shared__ float Ks[32][68];
    const int bh = blockIdx.z;
    const int b  = bh >> 4;
    const int h  = bh & 15;
    const int tid = threadIdx.x;
    const int tx = tid & 15;
    const int ty = tid >> 4;
    const int q0  = blockIdx.y * 128;
    const int kb0 = blockIdx.x * 64;

    float acc[8][4];
    #pragma unroll
    for (int i = 0; i < 8; i++)
        #pragma unroll
        for (int j = 0; j < 4; j++) acc[i][j] = 0.f;

    for (int k0 = 0; k0 < HDIM; k0 += 32) {
        #pragma unroll
        for (int i = 0; i < 4; i++) {
            int lin4 = i * 256 + tid;
            int qr = lin4 >> 3;
            int d4 = (lin4 & 7) << 2;
            *(float4*)&Qs[qr][d4] =
                *(const float4*)&g_q[((size_t)(b * NV + q0 + qr)) * EMBED + h * HDIM + k0 + d4];
        }
        #pragma unroll
        for (int i = 0; i < 2; i++) {
            int lin4 = i * 256 + tid;
            int kc = lin4 >> 3;
            int d4 = (lin4 & 7) << 2;
            float4 a = *(const float4*)&g_k[((size_t)(b * NL + kb0 + kc)) * EMBED + h * HDIM + k0 + d4];
            Ks[d4 + 0][kc] = a.x;
            Ks[d4 + 1][kc] = a.y;
            Ks[d4 + 2][kc] = a.z;
            Ks[d4 + 3][kc] = a.w;
        }
        __syncthreads();
        #pragma unroll
        for (int kd = 0; kd < 32; kd++) {
            float4 b4 = *(const float4*)&Ks[kd][tx * 4];
            #pragma unroll
            for (int i = 0; i < 8; i++) {
                float ra = Qs[ty * 8 + i][kd];
                acc[i][0] += ra * b4.x;
                acc[i][1] += ra * b4.y;
                acc[i][2] += ra * b4.z;
                acc[i][3] += ra * b4.w;
            }
        }
        __syncthreads();
    }
    #pragma unroll
    for (int i = 0; i < 8; i++) {
        float4 o = { acc[i][0] * 0.25f, acc[i][1] * 0.25f, acc[i][2] * 0.25f, acc[i][3] * 0.25f };
        *(float4*)&g_S[((size_t)bh * NV + q0 + ty * 8 + i) * NL + kb0 + tx * 4] = o;
    }
}

// ---------------- colstats ----------------
__global__ __launch_bounds__(1024) void colstats_kernel()
{
    __shared__ float sm[1024];
    __shared__ float ss[1024];
    const int bh  = blockIdx.x;
    const int tid = threadIdx.x;
    const int kk  = tid & 255;
    const int sub = tid >> 8;
    const float* Sb = g_S + (size_t)bh * NV * NL;

    float m = -3.0e38f, s = 0.f;
    for (int q = sub; q < NV; q += 4) {
        float x = Sb[(size_t)q * NL + kk];
        if (x > m) { s = s * __expf(m - x) + 1.f; m = x; }
        else       { s += __expf(x - m); }
    }
    sm[tid] = m; ss[tid] = s;
    __syncthreads();
    if (sub == 0) {
        float M0 = m, S0 = s;
        #pragma unroll
        for (int j = 1; j < 4; j++) {
            float m2 = sm[j * 256 + kk], s2 = ss[j * 256 + kk];
            float mm = fmaxf(M0, m2);
            S0 = S0 * __expf(M0 - mm) + s2 * __expf(m2 - mm);
            M0 = mm;
        }
        g_colm[bh * NL + kk] = M0;
        g_cols[bh * NL + kk] = S0;
    }
}

// ---------------- out_v ----------------
__global__ __launch_bounds__(256) void out_v_kernel(const int* __restrict__ mask)
{
    __shared__ float Vs[128][64];
    __shared__ float Ps[8][128];
    __shared__ float mb[256];
    const int bh = blockIdx.y;
    const int b  = bh >> 4;
    const int h  = bh & 15;
    const int tid  = threadIdx.x;
    const int w    = tid >> 5;
    const int lane = tid & 31;

    mb[tid] = (mask[b * NL + tid] == 0) ? -1.0e9f : 0.0f;
    __syncthreads();

    const float* Sbase = g_S + ((size_t)bh * NV + blockIdx.x * 64) * NL;

    float rm[8], ris[8];
    #pragma unroll
    for (int r = 0; r < 8; r++) {
        const float* Sr = Sbase + (size_t)(w * 8 + r) * NL;
        float sv[8], m = -3.0e38f;
        #pragma unroll
        for (int j = 0; j < 8; j++) {
            float x = Sr[lane + 32 * j] + mb[lane + 32 * j];
            sv[j] = x;
            m = fmaxf(m, x);
        }
        #pragma unroll
        for (int o = 16; o > 0; o >>= 1) m = fmaxf(m, __shfl_xor_sync(0xffffffffu, m, o));
        float s = 0.f;
        #pragma unroll
        for (int j = 0; j < 8; j++) s += __expf(sv[j] - m);
        #pragma unroll
        for (int o = 16; o > 0; o >>= 1) s += __shfl_xor_sync(0xffffffffu, s, o);
        rm[r]  = m;
        ris[r] = 1.0f / s;
    }

    float a0[8], a1[8];
    #pragma unroll
    for (int r = 0; r < 8; r++) { a0[r] = 0.f; a1[r] = 0.f; }

    for (int half = 0; half < 2; half++) {
        __syncthreads();
        #pragma unroll
        for (int i = 0; i < 8; i++) {
            int row = i * 16 + (tid >> 4);
            int col = (tid & 15) * 4;
            *(float4*)&Vs[row][col] =
                *(const float4*)&g_vall[((size_t)(b * NL + half * 128 + row)) * EMBED + h * HDIM + col];
        }
        __syncthreads();
        #pragma unroll
        for (int r = 0; r < 8; r++) {
            const float* Sr = Sbase + (size_t)(w * 8 + r) * NL + half * 128;
            #pragma unroll
            for (int j = 0; j < 4; j++) {
                int kk = lane + 32 * j;
                Ps[w][kk] = __expf(Sr[kk] + mb[half * 128 + kk] - rm[r]) * ris[r];
            }
            __syncwarp();
            #pragma unroll 8
            for (int kk = 0; kk < 128; kk++) {
                float pv = Ps[w][kk];
                a0[r] += pv * Vs[kk][lane];
                a1[r] += pv * Vs[kk][lane + 32];
            }
            __syncwarp();
        }
    }
    #pragma unroll
    for (int r = 0; r < 8; r++) {
        size_t base = ((size_t)(b * NV + blockIdx.x * 64 + w * 8 + r)) * EMBED + h * HDIM;
        g_ov[base + lane]      = a0[r];
        g_ov[base + 32 + lane] = a1[r];
    }
}

// ---------------- out_l ----------------
__global__ __launch_bounds__(256) void out_l_kernel()
{
    __shared__ float Ps[32][64];
    __shared__ float Vs[32][64];
    __shared__ float ms[64];
    __shared__ float iss[64];
    const int bh = blockIdx.y;
    const int b  = bh >> 4;
    const int h  = bh & 15;
    const int kb0 = blockIdx.x * 64;
    const int tid = threadIdx.x;
    const int tx = tid & 15;
    const int ty = tid >> 4;

    if (tid < 64) {
        ms[tid]  = g_colm[bh * NL + kb0 + tid];
        iss[tid] = 1.0f / g_cols[bh * NL + kb0 + tid];
    }
    __syncthreads();

    float acc[4][4];
    #pragma unroll
    for (int i = 0; i < 4; i++)
        #pragma unroll
        for (int j = 0; j < 4; j++) acc[i][j] = 0.f;

    for (int qc = 0; qc < NV; qc += 32) {
        #pragma unroll
        for (int i = 0; i < 8; i++) {
            int lin = i * 256 + tid;
            int qq = lin >> 6;
            int cc = lin & 63;
            float x = g_S[((size_t)bh * NV + qc + qq) * NL + kb0 + cc];
            Ps[qq][cc] = __expf(x - ms[cc]) * iss[cc];
            Vs[qq][cc] = g_valv[((size_t)(b * NV + qc + qq)) * EMBED + h * HDIM + cc];
        }
        __syncthreads();
        #pragma unroll
        for (int qq = 0; qq < 32; qq++) {
            float4 pa = *(const float4*)&Ps[qq][ty * 4];
            float4 pb = *(const float4*)&Vs[qq][tx * 4];
            acc[0][0] += pa.x * pb.x; acc[0][1] += pa.x * pb.y; acc[0][2] += pa.x * pb.z; acc[0][3] += pa.x * pb.w;
            acc[1][0] += pa.y * pb.x; acc[1][1] += pa.y * pb.y; acc[1][2] += pa.y * pb.z; acc[1][3] += pa.y * pb.w;
            acc[2][0] += pa.z * pb.x; acc[2][1] += pa.z * pb.y; acc[2][2] += pa.z * pb.z; acc[2][3] += pa.z * pb.w;
            acc[3][0] += pa.w * pb.x; acc[3][1] += pa.w * pb.y; acc[3][2] += pa.w * pb.z; acc[3][3] += pa.w * pb.w;
        }
        __syncthreads();
    }
    #pragma unroll
    for (int i = 0; i < 4; i++) {
        float4 o = { acc[i][0], acc[i][1], acc[i][2], acc[i][3] };
        *(float4*)&g_ol[((size_t)(b * NL + kb0 + ty * 4 + i)) * EMBED + h * HDIM + tx * 4] = o;
    }
}

// ---------------- host launcher ----------------
extern "C" void kernel_launch(void* const* d_in, const int* in_sizes, int n_in,
                              void* d_out, int out_size)
{
    (void)in_sizes; (void)n_in; (void)out_size;
    const float* v       = (const float*)d_in[0];
    const float* l       = (const float*)d_in[1];
    const int*   mask    = (const int*)  d_in[2];
    const float* W_v2q   = (const float*)d_in[3];
    const float* b_v2q   = (const float*)d_in[4];
    const float* W_l2k   = (const float*)d_in[5];
    const float* b_l2k   = (const float*)d_in[6];
    const float* W_v2v   = (const float*)d_in[7];
    const float* b_v2v   = (const float*)d_in[8];
    const float* W_l2v   = (const float*)d_in[9];
    const float* b_l2v   = (const float*)d_in[10];
    const float* W_v2out = (const float*)d_in[11];
    const float* b_v2out = (const float*)d_in[12];
    const float* W_l2out = (const float*)d_in[13];
    const float* b_l2out = (const float*)d_in[14];
    float* out = (float*)d_out;

    float *p_q, *p_valv, *p_k, *p_vall, *p_ov, *p_ol, *p_wt;
    cudaGetSymbolAddress((void**)&p_q,    g_q);
    cudaGetSymbolAddress((void**)&p_valv, g_valv);
    cudaGetSymbolAddress((void**)&p_k,    g_k);
    cudaGetSymbolAddress((void**)&p_vall, g_vall);
    cudaGetSymbolAddress((void**)&p_ov,   g_ov);
    cudaGetSymbolAddress((void**)&p_ol,   g_ol);
    cudaGetSymbolAddress((void**)&p_wt,   g_Wt);

    static int smem_set = 0;
    if (!smem_set) {
        cudaFuncSetAttribute(mma_gemm, cudaFuncAttributeMaxDynamicSharedMemorySize, GEMM_SMEM);
        smem_set = 1;
    }

    // weight transposes: Wt[n][k] = W[k][n]
    dim3 tb(32, 8);
    transpose_kn<<<dim3(EMBED / 32, EMBED / 32), tb>>>(W_v2q,   p_wt + WT_V2Q,   EMBED, EMBED);
    transpose_kn<<<dim3(EMBED / 32, LDIM / 32),  tb>>>(W_l2k,   p_wt + WT_L2K,   LDIM,  EMBED);
    transpose_kn<<<dim3(EMBED / 32, EMBED / 32), tb>>>(W_v2v,   p_wt + WT_V2V,   EMBED, EMBED);
    transpose_kn<<<dim3(EMBED / 32, LDIM / 32),  tb>>>(W_l2v,   p_wt + WT_L2V,   LDIM,  EMBED);
    transpose_kn<<<dim3(EMBED / 32, EMBED / 32), tb>>>(W_v2out, p_wt + WT_V2OUT, EMBED, EMBED);
    transpose_kn<<<dim3(LDIM / 32,  EMBED / 32), tb>>>(W_l2out, p_wt + WT_L2OUT, EMBED, LDIM);

    // input projections (tensor-core tf32 via mma.sync)
    mma_gemm<<<dim3(EMBED / 128, MV / 128), 256, GEMM_SMEM>>>(v, p_wt + WT_V2Q, b_v2q, p_q,    MV, EMBED, EMBED);
    mma_gemm<<<dim3(EMBED / 128, MV / 128), 256, GEMM_SMEM>>>(v, p_wt + WT_V2V, b_v2v, p_valv, MV, EMBED, EMBED);
    mma_gemm<<<dim3(EMBED / 128, ML / 128), 256, GEMM_SMEM>>>(l, p_wt + WT_L2K, b_l2k, p_k,    ML, EMBED, LDIM);
    mma_gemm<<<dim3(EMBED / 128, ML / 128), 256, GEMM_SMEM>>>(l, p_wt + WT_L2V, b_l2v, p_vall, ML, EMBED, LDIM);

    // attention
    scores_kernel  <<<dim3(NL / 64, NV / 128, BH), 256>>>();
    colstats_kernel<<<dim3(BH), 1024>>>();
    out_v_kernel   <<<dim3(NV / 64, BH), 256>>>(mask);
    out_l_kernel   <<<dim3(NL / 64, BH), 256>>>();

    // output projections
    mma_gemm<<<dim3(EMBED / 128, MV / 128), 256, GEMM_SMEM>>>(p_ov, p_wt + WT_V2OUT, b_v2out, out, MV, EMBED, EMBED);
    mma_gemm<<<dim3(LDIM / 128,  ML / 128), 256, GEMM_SMEM>>>(p_ol, p_wt + WT_L2OUT, b_l2out, out + (size_t)MV * EMBED, ML, LDIM, EMBED);
}

// round 4
// speedup vs baseline: 1.7484x; 1.0020x over previous
#include <cuda_runtime.h>
#include <cstdint>
#include <cstddef>

// ---------------- problem constants ----------------
#define BATCH   4
#define NV      4096
#define NL      256
#define EMBED   1024
#define HEADS   16
#define HDIM    64
#define LDIM    768
#define BH      (BATCH*HEADS)          // 64
#define MV      (BATCH*NV)             // 16384
#define ML      (BATCH*NL)             // 1024

// ---------------- scratch (device globals; no allocs allowed) ----------------
__device__ float g_q   [(size_t)MV*EMBED];   // 64 MB  vision queries
__device__ float g_valv[(size_t)MV*EMBED];   // 64 MB  vision values
__device__ float g_k   [(size_t)ML*EMBED];   // 4 MB   language keys
__device__ float g_vall[(size_t)ML*EMBED];   // 4 MB   language values
__device__ float g_S   [(size_t)BH*NV*NL];   // 256 MB raw scores (unmasked, scaled)
__device__ float g_ov  [(size_t)MV*EMBED];   // 64 MB  out_v heads
__device__ float g_ol  [(size_t)ML*EMBED];   // 4 MB   out_l heads
__device__ float g_colm[BH*NL];
__device__ float g_cols[BH*NL];
__device__ float g_Wt  [5505024];            // 21 MB transposed weights

// transposed-weight offsets (floats)
#define WT_V2Q   0
#define WT_L2K   1048576
#define WT_V2V   1835008
#define WT_L2V   2883584
#define WT_V2OUT 3670016
#define WT_L2OUT 4718592

// ---------------- weight transpose: Wt[n][k] = W[k][n] ----------------
__global__ void transpose_kn(const float* __restrict__ W, float* __restrict__ Wt, int K, int N)
{
    __shared__ float t[32][33];
    const int kb = blockIdx.y * 32, nb = blockIdx.x * 32;
    const int x = threadIdx.x, y = threadIdx.y;   // 32 x 8
    #pragma unroll
    for (int i = 0; i < 32; i += 8)
        t[y + i][x] = W[(size_t)(kb + y + i) * N + nb + x];
    __syncthreads();
    #pragma unroll
    for (int i = 0; i < 32; i += 8)
        Wt[(size_t)(nb + y + i) * K + kb + x] = t[x][y + i];
}

// ---------------- tf32 helpers ----------------
__device__ __forceinline__ float tf32_rn(float x) {
    uint32_t r;
    asm("cvt.rna.tf32.f32 %0, %1;" : "=r"(r) : "f"(x));
    return __uint_as_float(r);
}
__device__ __forceinline__ void mma_tf32(float* c, const uint32_t* a, const uint32_t* b) {
    asm volatile(
        "mma.sync.aligned.m16n8k8.row.col.f32.tf32.tf32.f32 "
        "{%0,%1,%2,%3}, {%4,%5,%6,%7}, {%8,%9}, {%0,%1,%2,%3};"
        : "+f"(c[0]), "+f"(c[1]), "+f"(c[2]), "+f"(c[3])
        : "r"(a[0]), "r"(a[1]), "r"(a[2]), "r"(a[3]), "r"(b[0]), "r"(b[1]));
}

// ---------------- tf32 mma.sync GEMM: C[M,N] = A[M,K] @ Bt[N,K]^T + bias[N] ----------------
// CTA 128x128, BK=32, 256 threads, 8 warps (2m x 4n), warp tile 64x32 = 4x4 m16n8k8.
// Double-buffered padded smem. Requires M%128==0, N%128==0, K%32==0.
#define ASTR   36                      // row stride in floats (+4 pad)
#define TBUF   (128*ASTR)              // 4608 floats per operand per stage

__global__ __launch_bounds__(256, 1) void mma_gemm(
    const float* __restrict__ A, const float* __restrict__ Bt,
    const float* __restrict__ bias, float* __restrict__ C,
    int M, int N, int K)
{
    extern __shared__ float smf[];
    float* As = smf;                   // [2][128][36]
    float* Bs = smf + 2 * TBUF;        // [2][128][36]
    __shared__ float sbias[128];

    const int tid  = threadIdx.x;
    const int w    = tid >> 5;
    const int lane = tid & 31;
    const int grp  = lane >> 2;
    const int tg   = lane & 3;
    const int wm   = (w & 1) * 64;
    const int wn   = (w >> 1) * 32;
    const int m0   = blockIdx.y * 128;
    const int n0   = blockIdx.x * 128;

    if (tid < 128) sbias[tid] = bias[n0 + tid];

    const float* Ab = A  + (size_t)m0 * K;
    const float* Bb = Bt + (size_t)n0 * K;
    const int ldr = tid >> 3;          // 0..31  (row block per 4-iter step)
    const int ldc = (tid & 7) * 4;     // 0..28

    float acc[4][4][4];
    #pragma unroll
    for (int i = 0; i < 4; i++)
        #pragma unroll
        for (int j = 0; j < 4; j++)
            #pragma unroll
            for (int t = 0; t < 4; t++) acc[i][j][t] = 0.f;

    const int NC = K / 32;

    // prologue: chunk 0 -> stage 0
    {
        #pragma unroll
        for (int i = 0; i < 4; i++) {
            int r = i * 32 + ldr;
            float4 va = *(const float4*)(Ab + (size_t)r * K + ldc);
            float4 vb = *(const float4*)(Bb + (size_t)r * K + ldc);
            float* da = As + r * ASTR + ldc;
            float* db = Bs + r * ASTR + ldc;
            da[0] = tf32_rn(va.x); da[1] = tf32_rn(va.y); da[2] = tf32_rn(va.z); da[3] = tf32_rn(va.w);
            db[0] = tf32_rn(vb.x); db[1] = tf32_rn(vb.y); db[2] = tf32_rn(vb.z); db[3] = tf32_rn(vb.w);
        }
    }
    __syncthreads();

    for (int c = 0; c < NC; c++) {
        const int b = c & 1;
        float4 pa[4], pb[4];
        if (c + 1 < NC) {
            const int k0 = (c + 1) * 32;
            #pragma unroll
            for (int i = 0; i < 4; i++) {
                int r = i * 32 + ldr;
                pa[i] = *(const float4*)(Ab + (size_t)r * K + k0 + ldc);
                pb[i] = *(const float4*)(Bb + (size_t)r * K + k0 + ldc);
            }
        }

        const float* Ac = As + b * TBUF;
        const float* Bc = Bs + b * TBUF;
        #pragma unroll
        for (int k0 = 0; k0 < 32; k0 += 8) {
            uint32_t af[4][4], bf[4][2];
            #pragma unroll
            for (int i = 0; i < 4; i++) {
                int row = wm + i * 16 + grp;
                af[i][0] = __float_as_uint(Ac[row * ASTR + k0 + tg]);
                af[i][1] = __float_as_uint(Ac[(row + 8) * ASTR + k0 + tg]);
                af[i][2] = __float_as_uint(Ac[row * ASTR + k0 + tg + 4]);
                af[i][3] = __float_as_uint(Ac[(row + 8) * ASTR + k0 + tg + 4]);
            }
            #pragma unroll
            for (int j = 0; j < 4; j++) {
                int n = wn + j * 8 + grp;
                bf[j][0] = __float_as_uint(Bc[n * ASTR + k0 + tg]);
                bf[j][1] = __float_as_uint(Bc[n * ASTR + k0 + tg + 4]);
            }
            #pragma unroll
            for (int i = 0; i < 4; i++)
                #pragma unroll
                for (int j = 0; j < 4; j++)
                    mma_tf32(acc[i][j], af[i], bf[j]);
        }

        if (c + 1 < NC) {
            __syncthreads();
            const int nb = 1 - b;
            float* da0 = As + nb * TBUF;
            float* db0 = Bs + nb * TBUF;
            #pragma unroll
            for (int i = 0; i < 4; i++) {
                int r = i * 32 + ldr;
                float* da = da0 + r * ASTR + ldc;
                float* db = db0 + r * ASTR + ldc;
                da[0] = tf32_rn(pa[i].x); da[1] = tf32_rn(pa[i].y); da[2] = tf32_rn(pa[i].z); da[3] = tf32_rn(pa[i].w);
                db[0] = tf32_rn(pb[i].x); db[1] = tf32_rn(pb[i].y); db[2] = tf32_rn(pb[i].z); db[3] = tf32_rn(pb[i].w);
            }
            __syncthreads();
        }
    }

    // epilogue
    #pragma unroll
    for (int i = 0; i < 4; i++) {
        int r0 = m0 + wm + i * 16 + grp;
        float* C0 = C + (size_t)r0 * N + n0;
        float* C1 = C + (size_t)(r0 + 8) * N + n0;
        #pragma unroll
        for (int j = 0; j < 4; j++) {
            int cc = wn + j * 8 + 2 * tg;
            float2 v0 = { acc[i][j][0] + sbias[cc], acc[i][j][1] + sbias[cc + 1] };
            float2 v1 = { acc[i][j][2] + sbias[cc], acc[i][j][3] + sbias[cc + 1] };
            *(float2*)(C0 + cc) = v0;
            *(float2*)(C1 + cc) = v1;
        }
    }
}
#define GEMM_SMEM (4 * TBUF * sizeof(float))   // 73728 bytes

// ---------------- scores: S[bh][q][k] = 0.25 * dot_d(q, k)  (UNMASKED) ----------------
__global__ __launch_bounds__(256) void scores_kernel()
{
    __shared__ float Qs[128][32];
    __shared__ float Ks[32][68];
    const int bh = blockIdx.z;
    const int b  = bh >> 4;
    const int h  = bh & 15;
    const int tid = threadIdx.x;
    const int tx = tid & 15;
    const int ty = tid >> 4;
    const int q0  = blockIdx.y * 128;
    const int kb0 = blockIdx.x * 64;

    float acc[8][4];
    #pragma unroll
    for (int i = 0; i < 8; i++)
        #pragma unroll
        for (int j = 0; j < 4; j++) acc[i][j] = 0.f;

    for (int k0 = 0; k0 < HDIM; k0 += 32) {
        #pragma unroll
        for (int i = 0; i < 4; i++) {
            int lin4 = i * 256 + tid;
            int qr = lin4 >> 3;
            int d4 = (lin4 & 7) << 2;
            *(float4*)&Qs[qr][d4] =
                *(const float4*)&g_q[((size_t)(b * NV + q0 + qr)) * EMBED + h * HDIM + k0 + d4];
        }
        #pragma unroll
        for (int i = 0; i < 2; i++) {
            int lin4 = i * 256 + tid;
            int kc = lin4 >> 3;
            int d4 = (lin4 & 7) << 2;
            float4 a = *(const float4*)&g_k[((size_t)(b * NL + kb0 + kc)) * EMBED + h * HDIM + k0 + d4];
            Ks[d4 + 0][kc] = a.x;
            Ks[d4 + 1][kc] = a.y;
            Ks[d4 + 2][kc] = a.z;
            Ks[d4 + 3][kc] = a.w;
        }
        __syncthreads();
        #pragma unroll
        for (int kd = 0; kd < 32; kd++) {
            float4 b4 = *(const float4*)&Ks[kd][tx * 4];
            #pragma unroll
            for (int i = 0; i < 8; i++) {
                float ra = Qs[ty * 8 + i][kd];
                acc[i][0] += ra * b4.x;
                acc[i][1] += ra * b4.y;
                acc[i][2] += ra * b4.z;
                acc[i][3] += ra * b4.w;
            }
        }
        __syncthreads();
    }
    #pragma unroll
    for (int i = 0; i < 8; i++) {
        float4 o = { acc[i][0] * 0.25f, acc[i][1] * 0.25f, acc[i][2] * 0.25f, acc[i][3] * 0.25f };
        *(float4*)&g_S[((size_t)bh * NV + q0 + ty * 8 + i) * NL + kb0 + tx * 4] = o;
    }
}

// ---------------- colstats ----------------
__global__ __launch_bounds__(1024) void colstats_kernel()
{
    __shared__ float sm[1024];
    __shared__ float ss[1024];
    const int bh  = blockIdx.x;
    const int tid = threadIdx.x;
    const int kk  = tid & 255;
    const int sub = tid >> 8;
    const float* Sb = g_S + (size_t)bh * NV * NL;

    float m = -3.0e38f, s = 0.f;
    for (int q = sub; q < NV; q += 4) {
        float x = Sb[(size_t)q * NL + kk];
        if (x > m) { s = s * __expf(m - x) + 1.f; m = x; }
        else       { s += __expf(x - m); }
    }
    sm[tid] = m; ss[tid] = s;
    __syncthreads();
    if (sub == 0) {
        float M0 = m, S0 = s;
        #pragma unroll
        for (int j = 1; j < 4; j++) {
            float m2 = sm[j * 256 + kk], s2 = ss[j * 256 + kk];
            float mm = fmaxf(M0, m2);
            S0 = S0 * __expf(M0 - mm) + s2 * __expf(m2 - mm);
            M0 = mm;
        }
        g_colm[bh * NL + kk] = M0;
        g_cols[bh * NL + kk] = S0;
    }
}

// ---------------- out_v ----------------
__global__ __launch_bounds__(256) void out_v_kernel(const int* __restrict__ mask)
{
    __shared__ float Vs[128][64];
    __shared__ float Ps[8][128];
    __shared__ float mb[256];
    const int bh = blockIdx.y;
    const int b  = bh >> 4;
    const int h  = bh & 15;
    const int tid  = threadIdx.x;
    const int w    = tid >> 5;
    const int lane = tid & 31;

    mb[tid] = (mask[b * NL + tid] == 0) ? -1.0e9f : 0.0f;
    __syncthreads();

    const float* Sbase = g_S + ((size_t)bh * NV + blockIdx.x * 64) * NL;

    float rm[8], ris[8];
    #pragma unroll
    for (int r = 0; r < 8; r++) {
        const float* Sr = Sbase + (size_t)(w * 8 + r) * NL;
        float sv[8], m = -3.0e38f;
        #pragma unroll
        for (int j = 0; j < 8; j++) {
            float x = Sr[lane + 32 * j] + mb[lane + 32 * j];
            sv[j] = x;
            m = fmaxf(m, x);
        }
        #pragma unroll
        for (int o = 16; o > 0; o >>= 1) m = fmaxf(m, __shfl_xor_sync(0xffffffffu, m, o));
        float s = 0.f;
        #pragma unroll
        for (int j = 0; j < 8; j++) s += __expf(sv[j] - m);
        #pragma unroll
        for (int o = 16; o > 0; o >>= 1) s += __shfl_xor_sync(0xffffffffu, s, o);
        rm[r]  = m;
        ris[r] = 1.0f / s;
    }

    float a0[8], a1[8];
    #pragma unroll
    for (int r = 0; r < 8; r++) { a0[r] = 0.f; a1[r] = 0.f; }

    for (int half = 0; half < 2; half++) {
        __syncthreads();
        #pragma unroll
        for (int i = 0; i < 8; i++) {
            int row = i * 16 + (tid >> 4);
            int col = (tid & 15) * 4;
            *(float4*)&Vs[row][col] =
                *(const float4*)&g_vall[((size_t)(b * NL + half * 128 + row)) * EMBED + h * HDIM + col];
        }
        __syncthreads();
        #pragma unroll
        for (int r = 0; r < 8; r++) {
            const float* Sr = Sbase + (size_t)(w * 8 + r) * NL + half * 128;
            #pragma unroll
            for (int j = 0; j < 4; j++) {
                int kk = lane + 32 * j;
                Ps[w][kk] = __expf(Sr[kk] + mb[half * 128 + kk] - rm[r]) * ris[r];
            }
            __syncwarp();
            #pragma unroll 8
            for (int kk = 0; kk < 128; kk++) {
                float pv = Ps[w][kk];
                a0[r] += pv * Vs[kk][lane];
                a1[r] += pv * Vs[kk][lane + 32];
            }
            __syncwarp();
        }
    }
    #pragma unroll
    for (int r = 0; r < 8; r++) {
        size_t base = ((size_t)(b * NV + blockIdx.x * 64 + w * 8 + r)) * EMBED + h * HDIM;
        g_ov[base + lane]      = a0[r];
        g_ov[base + 32 + lane] = a1[r];
    }
}

// ---------------- out_l ----------------
__global__ __launch_bounds__(256) void out_l_kernel()
{
    __shared__ float Ps[32][64];
    __shared__ float Vs[32][64];
    __shared__ float ms[64];
    __shared__ float iss[64];
    const int bh = blockIdx.y;
    const int b  = bh >> 4;
    const int h  = bh & 15;
    const int kb0 = blockIdx.x * 64;
    const int tid = threadIdx.x;
    const int tx = tid & 15;
    const int ty = tid >> 4;

    if (tid < 64) {
        ms[tid]  = g_colm[bh * NL + kb0 + tid];
        iss[tid] = 1.0f / g_cols[bh * NL + kb0 + tid];
    }
    __syncthreads();

    float acc[4][4];
    #pragma unroll
    for (int i = 0; i < 4; i++)
        #pragma unroll
        for (int j = 0; j < 4; j++) acc[i][j] = 0.f;

    for (int qc = 0; qc < NV; qc += 32) {
        #pragma unroll
        for (int i = 0; i < 8; i++) {
            int lin = i * 256 + tid;
            int qq = lin >> 6;
            int cc = lin & 63;
            float x = g_S[((size_t)bh * NV + qc + qq) * NL + kb0 + cc];
            Ps[qq][cc] = __expf(x - ms[cc]) * iss[cc];
            Vs[qq][cc] = g_valv[((size_t)(b * NV + qc + qq)) * EMBED + h * HDIM + cc];
        }
        __syncthreads();
        #pragma unroll
        for (int qq = 0; qq < 32; qq++) {
            float4 pa = *(const float4*)&Ps[qq][ty * 4];
            float4 pb = *(const float4*)&Vs[qq][tx * 4];
            acc[0][0] += pa.x * pb.x; acc[0][1] += pa.x * pb.y; acc[0][2] += pa.x * pb.z; acc[0][3] += pa.x * pb.w;
            acc[1][0] += pa.y * pb.x; acc[1][1] += pa.y * pb.y; acc[1][2] += pa.y * pb.z; acc[1][3] += pa.y * pb.w;
            acc[2][0] += pa.z * pb.x; acc[2][1] += pa.z * pb.y; acc[2][2] += pa.z * pb.z; acc[2][3] += pa.z * pb.w;
            acc[3][0] += pa.w * pb.x; acc[3][1] += pa.w * pb.y; acc[3][2] += pa.w * pb.z; acc[3][3] += pa.w * pb.w;
        }
        __syncthreads();
    }
    #pragma unroll
    for (int i = 0; i < 4; i++) {
        float4 o = { acc[i][0], acc[i][1], acc[i][2], acc[i][3] };
        *(float4*)&g_ol[((size_t)(b * NL + kb0 + ty * 4 + i)) * EMBED + h * HDIM + tx * 4] = o;
    }
}

// ---------------- host launcher ----------------
extern "C" void kernel_launch(void* const* d_in, const int* in_sizes, int n_in,
                              void* d_out, int out_size)
{
    (void)in_sizes; (void)n_in; (void)out_size;
    const float* v       = (const float*)d_in[0];
    const float* l       = (const float*)d_in[1];
    const int*   mask    = (const int*)  d_in[2];
    const float* W_v2q   = (const float*)d_in[3];
    const float* b_v2q   = (const float*)d_in[4];
    const float* W_l2k   = (const float*)d_in[5];
    const float* b_l2k   = (const float*)d_in[6];
    const float* W_v2v   = (const float*)d_in[7];
    const float* b_v2v   = (const float*)d_in[8];
    const float* W_l2v   = (const float*)d_in[9];
    const float* b_l2v   = (const float*)d_in[10];
    const float* W_v2out = (const float*)d_in[11];
    const float* b_v2out = (const float*)d_in[12];
    const float* W_l2out = (const float*)d_in[13];
    const float* b_l2out = (const float*)d_in[14];
    float* out = (float*)d_out;

    float *p_q, *p_valv, *p_k, *p_vall, *p_ov, *p_ol, *p_wt;
    cudaGetSymbolAddress((void**)&p_q,    g_q);
    cudaGetSymbolAddress((void**)&p_valv, g_valv);
    cudaGetSymbolAddress((void**)&p_k,    g_k);
    cudaGetSymbolAddress((void**)&p_vall, g_vall);
    cudaGetSymbolAddress((void**)&p_ov,   g_ov);
    cudaGetSymbolAddress((void**)&p_ol,   g_ol);
    cudaGetSymbolAddress((void**)&p_wt,   g_Wt);

    static int smem_set = 0;
    if (!smem_set) {
        cudaFuncSetAttribute(mma_gemm, cudaFuncAttributeMaxDynamicSharedMemorySize, GEMM_SMEM);
        smem_set = 1;
    }

    // weight transposes: Wt[n][k] = W[k][n]
    dim3 tb(32, 8);
    transpose_kn<<<dim3(EMBED / 32, EMBED / 32), tb>>>(W_v2q,   p_wt + WT_V2Q,   EMBED, EMBED);
    transpose_kn<<<dim3(EMBED / 32, LDIM / 32),  tb>>>(W_l2k,   p_wt + WT_L2K,   LDIM,  EMBED);
    transpose_kn<<<dim3(EMBED / 32, EMBED / 32), tb>>>(W_v2v,   p_wt + WT_V2V,   EMBED, EMBED);
    transpose_kn<<<dim3(EMBED / 32, LDIM / 32),  tb>>>(W_l2v,   p_wt + WT_L2V,   LDIM,  EMBED);
    transpose_kn<<<dim3(EMBED / 32, EMBED / 32), tb>>>(W_v2out, p_wt + WT_V2OUT, EMBED, EMBED);
    transpose_kn<<<dim3(LDIM / 32,  EMBED / 32), tb>>>(W_l2out, p_wt + WT_L2OUT, EMBED, LDIM);

    // input projections (tensor-core tf32 via mma.sync)
    mma_gemm<<<dim3(EMBED / 128, MV / 128), 256, GEMM_SMEM>>>(v, p_wt + WT_V2Q, b_v2q, p_q,    MV, EMBED, EMBED);
    mma_gemm<<<dim3(EMBED / 128, MV / 128), 256, GEMM_SMEM>>>(v, p_wt + WT_V2V, b_v2v, p_valv, MV, EMBED, EMBED);
    mma_gemm<<<dim3(EMBED / 128, ML / 128), 256, GEMM_SMEM>>>(l, p_wt + WT_L2K, b_l2k, p_k,    ML, EMBED, LDIM);
    mma_gemm<<<dim3(EMBED / 128, ML / 128), 256, GEMM_SMEM>>>(l, p_wt + WT_L2V, b_l2v, p_vall, ML, EMBED, LDIM);

    // attention
    scores_kernel  <<<dim3(NL / 64, NV / 128, BH), 256>>>();
    colstats_kernel<<<dim3(BH), 1024>>>();
    out_v_kernel   <<<dim3(NV / 64, BH), 256>>>(mask);
    out_l_kernel   <<<dim3(NL / 64, BH), 256>>>();

    // output projections
    mma_gemm<<<dim3(EMBED / 128, MV / 128), 256, GEMM_SMEM>>>(p_ov, p_wt + WT_V2OUT, b_v2out, out, MV, EMBED, EMBED);
    mma_gemm<<<dim3(LDIM / 128,  ML / 128), 256, GEMM_SMEM>>>(p_ol, p_wt + WT_L2OUT, b_l2out, out + (size_t)MV * EMBED, ML, LDIM, EMBED);
}

// round 6
// speedup vs baseline: 1.9304x; 1.1041x over previous
#include <cuda_runtime.h>
#include <cuda_bf16.h>
#include <cstdint>
#include <cstddef>

#define BATCH   4
#define NV      4096
#define NL      256
#define EMBED   1024
#define HEADS   16
#define HDIM    64
#define LDIM    768
#define BH      (BATCH*HEADS)
#define MV      (BATCH*NV)
#define ML      (BATCH*NL)

// ---------------- scratch ----------------
__device__ float g_q   [(size_t)MV*EMBED];
__device__ float g_valv[(size_t)MV*EMBED];
__device__ float g_k   [(size_t)ML*EMBED];
__device__ float g_vall[(size_t)ML*EMBED];
__device__ float g_S   [(size_t)BH*NV*NL];
__device__ float g_ov  [(size_t)MV*EMBED];
__device__ float g_ol  [(size_t)ML*EMBED];
__device__ float g_colm[BH*NL];
__device__ float g_cols[BH*NL];
__device__ float g_pm  [32*BH*NL];
__device__ float g_ps  [32*BH*NL];
__device__ float g_Wt  [5505024];
__device__ __align__(16) uint32_t g_qs[(size_t)BH*NV*64];  // [plane][q][hi32|lo32] bf16 pairs
__device__ __align__(16) uint32_t g_ks[(size_t)BH*NL*64];

#define WT_V2Q   0
#define WT_L2K   1048576
#define WT_V2V   1835008
#define WT_L2V   2883584
#define WT_V2OUT 3670016
#define WT_L2OUT 4718592

// ---------------- fused weight transposes ----------------
struct TP6 { const float* W[6]; float* Wt[6]; int K[6]; int N[6]; };
__global__ void transpose6(TP6 tp)
{
    __shared__ float t[32][33];
    const int id = blockIdx.z;
    const int K = tp.K[id], N = tp.N[id];
    const int kb = blockIdx.y * 32, nb = blockIdx.x * 32;
    if (kb >= K || nb >= N) return;
    const float* W = tp.W[id];
    float* Wt = tp.Wt[id];
    const int x = threadIdx.x, y = threadIdx.y;
    #pragma unroll
    for (int i = 0; i < 32; i += 8)
        t[y + i][x] = W[(size_t)(kb + y + i) * N + nb + x];
    __syncthreads();
    #pragma unroll
    for (int i = 0; i < 32; i += 8)
        Wt[(size_t)(nb + y + i) * K + kb + x] = t[x][y + i];
}

// ---------------- helpers ----------------
__device__ __forceinline__ float tf32_rn(float x) {
    uint32_t r; asm("cvt.rna.tf32.f32 %0, %1;" : "=r"(r) : "f"(x));
    return __uint_as_float(r);
}
__device__ __forceinline__ void mma_tf32(float* c, const uint32_t* a, const uint32_t* b) {
    asm volatile("mma.sync.aligned.m16n8k8.row.col.f32.tf32.tf32.f32 "
        "{%0,%1,%2,%3}, {%4,%5,%6,%7}, {%8,%9}, {%0,%1,%2,%3};"
        : "+f"(c[0]), "+f"(c[1]), "+f"(c[2]), "+f"(c[3])
        : "r"(a[0]), "r"(a[1]), "r"(a[2]), "r"(a[3]), "r"(b[0]), "r"(b[1]));
}
__device__ __forceinline__ void mma_bf16(float* c, const uint32_t* a, uint32_t b0, uint32_t b1) {
    asm volatile("mma.sync.aligned.m16n8k16.row.col.f32.bf16.bf16.f32 "
        "{%0,%1,%2,%3}, {%4,%5,%6,%7}, {%8,%9}, {%0,%1,%2,%3};"
        : "+f"(c[0]), "+f"(c[1]), "+f"(c[2]), "+f"(c[3])
        : "r"(a[0]), "r"(a[1]), "r"(a[2]), "r"(a[3]), "r"(b0), "r"(b1));
}
__device__ __forceinline__ uint32_t pack_bf(float even, float odd) {
    uint32_t r; asm("cvt.rn.bf16x2.f32 %0, %1, %2;" : "=r"(r) : "f"(odd), "f"(even));
    return r;   // low half = even element
}

// ---------------- split fp32 -> bf16 hi/lo packed planes ----------------
__global__ void split_pack(const float* __restrict__ src, uint32_t* __restrict__ dst,
                           int rowsPerPlane, int rpShift)
{
    int idx = blockIdx.x * 256 + threadIdx.x;
    int quad = idx & 7;
    int R = idx >> 3;
    int p = R >> rpShift;
    int q = R & (rowsPerPlane - 1);
    int b = p >> 4, h = p & 15;
    const float* s = src + ((size_t)(b * rowsPerPlane + q)) * EMBED + h * 64 + quad * 8;
    float4 x0 = *(const float4*)s;
    float4 x1 = *(const float4*)(s + 4);
    uint32_t hi[4], lo[4];
    float e[8] = { x0.x, x0.y, x0.z, x0.w, x1.x, x1.y, x1.z, x1.w };
    #pragma unroll
    for (int i = 0; i < 4; i++) {
        hi[i] = pack_bf(e[2*i], e[2*i+1]);
        float fe = __uint_as_float(hi[i] << 16);
        float fo = __uint_as_float(hi[i] & 0xffff0000u);
        lo[i] = pack_bf(e[2*i] - fe, e[2*i+1] - fo);
    }
    uint32_t* d = dst + (size_t)R * 64;
    *(uint4*)(d + quad * 4)      = *(uint4*)hi;
    *(uint4*)(d + 32 + quad * 4) = *(uint4*)lo;
}

// ---------------- tf32 mma.sync GEMM (projections) ----------------
#define ASTR   36
#define TBUF   (128*ASTR)
__global__ __launch_bounds__(256, 1) void mma_gemm(
    const float* __restrict__ A, const float* __restrict__ Bt,
    const float* __restrict__ bias, float* __restrict__ C,
    int M, int N, int K)
{
    extern __shared__ float smf[];
    float* As = smf;
    float* Bs = smf + 2 * TBUF;
    __shared__ float sbias[128];
    const int tid = threadIdx.x, w = tid >> 5, lane = tid & 31;
    const int grp = lane >> 2, tg = lane & 3;
    const int wm = (w & 1) * 64, wn = (w >> 1) * 32;
    const int m0 = blockIdx.y * 128, n0 = blockIdx.x * 128;
    if (tid < 128) sbias[tid] = bias[n0 + tid];
    const float* Ab = A + (size_t)m0 * K;
    const float* Bb = Bt + (size_t)n0 * K;
    const int ldr = tid >> 3, ldc = (tid & 7) * 4;
    float acc[4][4][4];
    #pragma unroll
    for (int i = 0; i < 4; i++)
        #pragma unroll
        for (int j = 0; j < 4; j++)
            #pragma unroll
            for (int t = 0; t < 4; t++) acc[i][j][t] = 0.f;
    const int NC = K / 32;
    #pragma unroll
    for (int i = 0; i < 4; i++) {
        int r = i * 32 + ldr;
        float4 va = *(const float4*)(Ab + (size_t)r * K + ldc);
        float4 vb = *(const float4*)(Bb + (size_t)r * K + ldc);
        float* da = As + r * ASTR + ldc;
        float* db = Bs + r * ASTR + ldc;
        da[0]=tf32_rn(va.x); da[1]=tf32_rn(va.y); da[2]=tf32_rn(va.z); da[3]=tf32_rn(va.w);
        db[0]=tf32_rn(vb.x); db[1]=tf32_rn(vb.y); db[2]=tf32_rn(vb.z); db[3]=tf32_rn(vb.w);
    }
    __syncthreads();
    for (int c = 0; c < NC; c++) {
        const int b = c & 1;
        float4 pa[4], pb[4];
        if (c + 1 < NC) {
            const int k0 = (c + 1) * 32;
            #pragma unroll
            for (int i = 0; i < 4; i++) {
                int r = i * 32 + ldr;
                pa[i] = *(const float4*)(Ab + (size_t)r * K + k0 + ldc);
                pb[i] = *(const float4*)(Bb + (size_t)r * K + k0 + ldc);
            }
        }
        const float* Ac = As + b * TBUF;
        const float* Bc = Bs + b * TBUF;
        #pragma unroll
        for (int k0 = 0; k0 < 32; k0 += 8) {
            uint32_t af[4][4], bf[4][2];
            #pragma unroll
            for (int i = 0; i < 4; i++) {
                int row = wm + i * 16 + grp;
                af[i][0] = __float_as_uint(Ac[row * ASTR + k0 + tg]);
                af[i][1] = __float_as_uint(Ac[(row + 8) * ASTR + k0 + tg]);
                af[i][2] = __float_as_uint(Ac[row * ASTR + k0 + tg + 4]);
                af[i][3] = __float_as_uint(Ac[(row + 8) * ASTR + k0 + tg + 4]);
            }
            #pragma unroll
            for (int j = 0; j < 4; j++) {
                int n = wn + j * 8 + grp;
                bf[j][0] = __float_as_uint(Bc[n * ASTR + k0 + tg]);
                bf[j][1] = __float_as_uint(Bc[n * ASTR + k0 + tg + 4]);
            }
            #pragma unroll
            for (int i = 0; i < 4; i++)
                #pragma unroll
                for (int j = 0; j < 4; j++)
                    mma_tf32(acc[i][j], af[i], bf[j]);
        }
        if (c + 1 < NC) {
            __syncthreads();
            const int nb = 1 - b;
            float* da0 = As + nb * TBUF;
            float* db0 = Bs + nb * TBUF;
            #pragma unroll
            for (int i = 0; i < 4; i++) {
                int r = i * 32 + ldr;
                float* da = da0 + r * ASTR + ldc;
                float* db = db0 + r * ASTR + ldc;
                da[0]=tf32_rn(pa[i].x); da[1]=tf32_rn(pa[i].y); da[2]=tf32_rn(pa[i].z); da[3]=tf32_rn(pa[i].w);
                db[0]=tf32_rn(pb[i].x); db[1]=tf32_rn(pb[i].y); db[2]=tf32_rn(pb[i].z); db[3]=tf32_rn(pb[i].w);
            }
            __syncthreads();
        }
    }
    #pragma unroll
    for (int i = 0; i < 4; i++) {
        int r0 = m0 + wm + i * 16 + grp;
        float* C0 = C + (size_t)r0 * N + n0;
        float* C1 = C + (size_t)(r0 + 8) * N + n0;
        #pragma unroll
        for (int j = 0; j < 4; j++) {
            int cc = wn + j * 8 + 2 * tg;
            float2 v0 = { acc[i][j][0] + sbias[cc], acc[i][j][1] + sbias[cc + 1] };
            float2 v1 = { acc[i][j][2] + sbias[cc], acc[i][j][3] + sbias[cc + 1] };
            *(float2*)(C0 + cc) = v0;
            *(float2*)(C1 + cc) = v1;
        }
    }
}
#define GEMM_SMEM (4 * TBUF * sizeof(float))

// ---------------- scores via bf16x3 mma + fused col-stat partials ----------------
#define SSTR 68
#define SC_SMEM (2*128*SSTR*4 + 4*128*4)
__global__ __launch_bounds__(256, 1) void scores_mma()
{
    extern __shared__ uint32_t su[];
    uint32_t* As = su;
    uint32_t* Bs = su + 128 * SSTR;
    float* red = (float*)(su + 2 * 128 * SSTR);
    const int tid = threadIdx.x, w = tid >> 5, lane = tid & 31;
    const int grp = lane >> 2, tg = lane & 3;
    const int wq = w >> 1, wk = w & 1;
    const int p = blockIdx.z;
    const int q0 = blockIdx.y * 128, k0 = blockIdx.x * 128;

    const uint4* sa = (const uint4*)(g_qs + ((size_t)p * NV + q0) * 64);
    const uint4* sb = (const uint4*)(g_ks + ((size_t)p * NL + k0) * 64);
    #pragma unroll
    for (int i = 0; i < 8; i++) {
        int L = i * 256 + tid;
        int r = L >> 4, c = L & 15;
        *(uint4*)(As + r * SSTR + c * 4) = sa[r * 16 + c];
        *(uint4*)(Bs + r * SSTR + c * 4) = sb[r * 16 + c];
    }
    __syncthreads();

    float acc[2][8][4];
    #pragma unroll
    for (int i = 0; i < 2; i++)
        #pragma unroll
        for (int j = 0; j < 8; j++)
            #pragma unroll
            for (int t = 0; t < 4; t++) acc[i][j][t] = 0.f;

    #pragma unroll
    for (int s = 0; s < 12; s++) {
        const int seg = s >> 2, ss = (s & 3) * 8;
        const int ab = (seg == 2) ? 32 + ss : ss;
        const int bb = (seg == 1) ? 32 + ss : ss;
        uint32_t a[2][4], bf[8][2];
        #pragma unroll
        for (int i = 0; i < 2; i++) {
            int row = wq * 32 + i * 16 + grp;
            a[i][0] = As[row * SSTR + ab + tg];
            a[i][1] = As[(row + 8) * SSTR + ab + tg];
            a[i][2] = As[row * SSTR + ab + 4 + tg];
            a[i][3] = As[(row + 8) * SSTR + ab + 4 + tg];
        }
        #pragma unroll
        for (int j = 0; j < 8; j++) {
            int n = wk * 64 + j * 8 + grp;
            bf[j][0] = Bs[n * SSTR + bb + tg];
            bf[j][1] = Bs[n * SSTR + bb + 4 + tg];
        }
        #pragma unroll
        for (int i = 0; i < 2; i++)
            #pragma unroll
            for (int j = 0; j < 8; j++)
                mma_bf16(acc[i][j], a[i], bf[j][0], bf[j][1]);
    }

    #pragma unroll
    for (int i = 0; i < 2; i++)
        #pragma unroll
        for (int j = 0; j < 8; j++)
            #pragma unroll
            for (int t = 0; t < 4; t++) acc[i][j][t] *= 0.25f;

    #pragma unroll
    for (int i = 0; i < 2; i++)
        #pragma unroll
        for (int h2 = 0; h2 < 2; h2++) {
            int rq = q0 + wq * 32 + i * 16 + grp + h2 * 8;
            float* Sr = g_S + ((size_t)p * NV + rq) * NL + k0 + wk * 64;
            #pragma unroll
            for (int j = 0; j < 8; j++) {
                float2 v = { acc[i][j][h2 * 2], acc[i][j][h2 * 2 + 1] };
                *(float2*)(Sr + j * 8 + 2 * tg) = v;
            }
        }

    float cm[8][2];
    #pragma unroll
    for (int j = 0; j < 8; j++)
        #pragma unroll
        for (int par = 0; par < 2; par++) {
            float m = fmaxf(fmaxf(acc[0][j][par], acc[0][j][2 + par]),
                            fmaxf(acc[1][j][par], acc[1][j][2 + par]));
            #pragma unroll
            for (int o = 4; o <= 16; o <<= 1) m = fmaxf(m, __shfl_xor_sync(0xffffffffu, m, o));
            cm[j][par] = m;
        }
    if (grp == 0)
        #pragma unroll
        for (int j = 0; j < 8; j++)
            #pragma unroll
            for (int par = 0; par < 2; par++)
                red[wq * 128 + wk * 64 + j * 8 + 2 * tg + par] = cm[j][par];
    __syncthreads();
    float tmreg = 0.f;
    if (tid < 128)
        tmreg = fmaxf(fmaxf(red[tid], red[128 + tid]), fmaxf(red[256 + tid], red[384 + tid]));
    __syncthreads();
    if (tid < 128) red[tid] = tmreg;
    __syncthreads();
    float tmv[8][2];
    #pragma unroll
    for (int j = 0; j < 8; j++)
        #pragma unroll
        for (int par = 0; par < 2; par++)
            tmv[j][par] = red[wk * 64 + j * 8 + 2 * tg + par];
    __syncthreads();
    #pragma unroll
    for (int j = 0; j < 8; j++)
        #pragma unroll
        for (int par = 0; par < 2; par++) {
            float s = __expf(acc[0][j][par] - tmv[j][par]) + __expf(acc[0][j][2 + par] - tmv[j][par])
                    + __expf(acc[1][j][par] - tmv[j][par]) + __expf(acc[1][j][2 + par] - tmv[j][par]);
            #pragma unroll
            for (int o = 4; o <= 16; o <<= 1) s += __shfl_xor_sync(0xffffffffu, s, o);
            cm[j][par] = s;
        }
    if (grp == 0)
        #pragma unroll
        for (int j = 0; j < 8; j++)
            #pragma unroll
            for (int par = 0; par < 2; par++)
                red[wq * 128 + wk * 64 + j * 8 + 2 * tg + par] = cm[j][par];
    __syncthreads();
    if (tid < 128) {
        float s = red[tid] + red[128 + tid] + red[256 + tid] + red[384 + tid];
        size_t o = ((size_t)blockIdx.y * BH + p) * NL + k0 + tid;
        g_pm[o] = tmreg;
        g_ps[o] = s;
    }
}

// ---------------- combine 32 qtile partials -> colm/cols ----------------
__global__ void colcombine()
{
    const int p = blockIdx.x, col = threadIdx.x;
    float m = -3.0e38f;
    #pragma unroll 8
    for (int t = 0; t < 32; t++)
        m = fmaxf(m, g_pm[((size_t)t * BH + p) * NL + col]);
    float s = 0.f;
    #pragma unroll 8
    for (int t = 0; t < 32; t++) {
        size_t o = ((size_t)t * BH + p) * NL + col;
        s += __expf(g_pm[o] - m) * g_ps[o];
    }
    g_colm[p * NL + col] = m;
    g_cols[p * NL + col] = s;
}

// ---------------- out_v: single-pass row softmax + @Vl ----------------
#define OV_SMEM ((256*64 + 8*256 + 256) * 4)
__global__ __launch_bounds__(256, 1) void out_v2(const int* __restrict__ mask)
{
    extern __shared__ float ovs[];
    float* Vs = ovs;
    float* Ps = ovs + 16384;
    float* mbp = ovs + 18432;
    const int bh = blockIdx.y, b = bh >> 4, h = bh & 15;
    const int tid = threadIdx.x, w = tid >> 5, lane = tid & 31;
    mbp[tid] = (mask[b * NL + tid] == 0) ? -1.0e9f : 0.0f;
    #pragma unroll
    for (int i = 0; i < 16; i++) {
        int L = i * 256 + tid;
        int r = L >> 4, c = (L & 15) * 4;
        *(float4*)&Vs[r * 64 + c] =
            *(const float4*)&g_vall[((size_t)(b * NL + r)) * EMBED + h * 64 + c];
    }
    __syncthreads();
    const float* Sbase = g_S + ((size_t)bh * NV + blockIdx.x * 64) * NL;
    for (int r = 0; r < 8; r++) {
        const float* Sr = Sbase + (size_t)(w * 8 + r) * NL;
        float sv[8], m = -3.0e38f;
        #pragma unroll
        for (int j = 0; j < 8; j++) {
            sv[j] = Sr[lane + 32 * j] + mbp[lane + 32 * j];
            m = fmaxf(m, sv[j]);
        }
        #pragma unroll
        for (int o = 16; o > 0; o >>= 1) m = fmaxf(m, __shfl_xor_sync(0xffffffffu, m, o));
        float s = 0.f;
        #pragma unroll
        for (int j = 0; j < 8; j++) { sv[j] = __expf(sv[j] - m); s += sv[j]; }
        #pragma unroll
        for (int o = 16; o > 0; o >>= 1) s += __shfl_xor_sync(0xffffffffu, s, o);
        const float inv = 1.0f / s;
        #pragma unroll
        for (int j = 0; j < 8; j++) Ps[w * 256 + lane + 32 * j] = sv[j] * inv;
        __syncwarp();
        float a0 = 0.f, a1 = 0.f;
        #pragma unroll 8
        for (int k = 0; k < 256; k++) {
            float pv = Ps[w * 256 + k];
            a0 += pv * Vs[k * 64 + lane];
            a1 += pv * Vs[k * 64 + lane + 32];
        }
        size_t base = ((size_t)(b * NV + blockIdx.x * 64 + w * 8 + r)) * EMBED + h * 64;
        g_ov[base + lane] = a0;
        g_ov[base + 32 + lane] = a1;
        __syncwarp();
    }
}

// ---------------- out_l ----------------
__global__ __launch_bounds__(256) void out_l_kernel()
{
    __shared__ float Ps[32][64];
    __shared__ float Vs[32][64];
    __shared__ float ms[64];
    __shared__ float iss[64];
    const int bh = blockIdx.y, b = bh >> 4, h = bh & 15;
    const int kb0 = blockIdx.x * 64;
    const int tid = threadIdx.x, tx = tid & 15, ty = tid >> 4;
    if (tid < 64) {
        ms[tid] = g_colm[bh * NL + kb0 + tid];
        iss[tid] = 1.0f / g_cols[bh * NL + kb0 + tid];
    }
    __syncthreads();
    float acc[4][4];
    #pragma unroll
    for (int i = 0; i < 4; i++)
        #pragma unroll
        for (int j = 0; j < 4; j++) acc[i][j] = 0.f;
    for (int qc = 0; qc < NV; qc += 32) {
        #pragma unroll
        for (int i = 0; i < 8; i++) {
            int lin = i * 256 + tid;
            int qq = lin >> 6, cc = lin & 63;
            float x = g_S[((size_t)bh * NV + qc + qq) * NL + kb0 + cc];
            Ps[qq][cc] = __expf(x - ms[cc]) * iss[cc];
            Vs[qq][cc] = g_valv[((size_t)(b * NV + qc + qq)) * EMBED + h * 64 + cc];
        }
        __syncthreads();
        #pragma unroll
        for (int qq = 0; qq < 32; qq++) {
            float4 pa = *(const float4*)&Ps[qq][ty * 4];
            float4 pb = *(const float4*)&Vs[qq][tx * 4];
            acc[0][0]+=pa.x*pb.x; acc[0][1]+=pa.x*pb.y; acc[0][2]+=pa.x*pb.z; acc[0][3]+=pa.x*pb.w;
            acc[1][0]+=pa.y*pb.x; acc[1][1]+=pa.y*pb.y; acc[1][2]+=pa.y*pb.z; acc[1][3]+=pa.y*pb.w;
            acc[2][0]+=pa.z*pb.x; acc[2][1]+=pa.z*pb.y; acc[2][2]+=pa.z*pb.z; acc[2][3]+=pa.z*pb.w;
            acc[3][0]+=pa.w*pb.x; acc[3][1]+=pa.w*pb.y; acc[3][2]+=pa.w*pb.z; acc[3][3]+=pa.w*pb.w;
        }
        __syncthreads();
    }
    #pragma unroll
    for (int i = 0; i < 4; i++) {
        float4 o = { acc[i][0], acc[i][1], acc[i][2], acc[i][3] };
        *(float4*)&g_ol[((size_t)(b * NL + kb0 + ty * 4 + i)) * EMBED + h * 64 + tx * 4] = o;
    }
}

// ---------------- host launcher ----------------
extern "C" void kernel_launch(void* const* d_in, const int* in_sizes, int n_in,
                              void* d_out, int out_size)
{
    (void)in_sizes; (void)n_in; (void)out_size;
    const float* v       = (const float*)d_in[0];
    const float* l       = (const float*)d_in[1];
    const int*   mask    = (const int*)  d_in[2];
    const float* W_v2q   = (const float*)d_in[3];
    const float* b_v2q   = (const float*)d_in[4];
    const float* W_l2k   = (const float*)d_in[5];
    const float* b_l2k   = (const float*)d_in[6];
    const float* W_v2v   = (const float*)d_in[7];
    const float* b_v2v   = (const float*)d_in[8];
    const float* W_l2v   = (const float*)d_in[9];
    const float* b_l2v   = (const float*)d_in[10];
    const float* W_v2out = (const float*)d_in[11];
    const float* b_v2out = (const float*)d_in[12];
    const float* W_l2out = (const float*)d_in[13];
    const float* b_l2out = (const float*)d_in[14];
    float* out = (float*)d_out;

    float *p_q, *p_valv, *p_k, *p_vall, *p_ov, *p_ol, *p_wt;
    uint32_t *p_qs, *p_ks;
    cudaGetSymbolAddress((void**)&p_q,    g_q);
    cudaGetSymbolAddress((void**)&p_valv, g_valv);
    cudaGetSymbolAddress((void**)&p_k,    g_k);
    cudaGetSymbolAddress((void**)&p_vall, g_vall);
    cudaGetSymbolAddress((void**)&p_ov,   g_ov);
    cudaGetSymbolAddress((void**)&p_ol,   g_ol);
    cudaGetSymbolAddress((void**)&p_wt,   g_Wt);
    cudaGetSymbolAddress((void**)&p_qs,   g_qs);
    cudaGetSymbolAddress((void**)&p_ks,   g_ks);

    static int attr_set = 0;
    if (!attr_set) {
        cudaFuncSetAttribute(mma_gemm,   cudaFuncAttributeMaxDynamicSharedMemorySize, GEMM_SMEM);
        cudaFuncSetAttribute(scores_mma, cudaFuncAttributeMaxDynamicSharedMemorySize, SC_SMEM);
        cudaFuncSetAttribute(out_v2,     cudaFuncAttributeMaxDynamicSharedMemorySize, OV_SMEM);
        attr_set = 1;
    }

    // 0: all weight transposes in one launch
    TP6 tp;
    tp.W[0]=W_v2q;  tp.Wt[0]=p_wt+WT_V2Q;   tp.K[0]=EMBED; tp.N[0]=EMBED;
    tp.W[1]=W_l2k;  tp.Wt[1]=p_wt+WT_L2K;   tp.K[1]=LDIM;  tp.N[1]=EMBED;
    tp.W[2]=W_v2v;  tp.Wt[2]=p_wt+WT_V2V;   tp.K[2]=EMBED; tp.N[2]=EMBED;
    tp.W[3]=W_l2v;  tp.Wt[3]=p_wt+WT_L2V;   tp.K[3]=LDIM;  tp.N[3]=EMBED;
    tp.W[4]=W_v2out;tp.Wt[4]=p_wt+WT_V2OUT; tp.K[4]=EMBED; tp.N[4]=EMBED;
    tp.W[5]=W_l2out;tp.Wt[5]=p_wt+WT_L2OUT; tp.K[5]=EMBED; tp.N[5]=LDIM;   // FIX: W_l2out is [EMBED, LDIM]
    transpose6<<<dim3(32, 32, 6), dim3(32, 8)>>>(tp);

    // 1-2: language projections
    mma_gemm<<<dim3(EMBED/128, ML/128), 256, GEMM_SMEM>>>(l, p_wt+WT_L2K, b_l2k, p_k,    ML, EMBED, LDIM);
    mma_gemm<<<dim3(EMBED/128, ML/128), 256, GEMM_SMEM>>>(l, p_wt+WT_L2V, b_l2v, p_vall, ML, EMBED, LDIM);
    // 3: split K
    split_pack<<<(BH*NL*8)/256, 256>>>(p_k, p_ks, NL, 8);
    // 4-5: vision projections (launch #5 = big mma_gemm, profiled by ncu)
    mma_gemm<<<dim3(EMBED/128, MV/128), 256, GEMM_SMEM>>>(v, p_wt+WT_V2Q, b_v2q, p_q,    MV, EMBED, EMBED);
    mma_gemm<<<dim3(EMBED/128, MV/128), 256, GEMM_SMEM>>>(v, p_wt+WT_V2V, b_v2v, p_valv, MV, EMBED, EMBED);
    // 6: split Q
    split_pack<<<(BH*NV*8)/256, 256>>>(p_q, p_qs, NV, 12);
    // 7: scores + col-stat partials
    scores_mma<<<dim3(NL/128, NV/128, BH), 256, SC_SMEM>>>();
    // 8: combine stats
    colcombine<<<BH, NL>>>();
    // 9-10: attention outputs
    out_v2<<<dim3(NV/64, BH), 256, OV_SMEM>>>(mask);
    out_l_kernel<<<dim3(NL/64, BH), 256>>>();
    // 11-12: output projections
    mma_gemm<<<dim3(EMBED/128, MV/128), 256, GEMM_SMEM>>>(p_ov, p_wt+WT_V2OUT, b_v2out, out, MV, EMBED, EMBED);
    mma_gemm<<<dim3(LDIM/128,  ML/128), 256, GEMM_SMEM>>>(p_ol, p_wt+WT_L2OUT, b_l2out, out + (size_t)MV*EMBED, ML, LDIM, EMBED);
}

// round 8
// speedup vs baseline: 1.9825x; 1.0269x over previous
#include <cuda_runtime.h>
#include <cuda_bf16.h>
#include <cstdint>
#include <cstddef>

#define BATCH   4
#define NV      4096
#define NL      256
#define EMBED   1024
#define HEADS   16
#define HDIM    64
#define LDIM    768
#define BH      (BATCH*HEADS)
#define MV      (BATCH*NV)
#define ML      (BATCH*NL)

// ---------------- scratch ----------------
__device__ float g_q   [(size_t)MV*EMBED];
__device__ float g_valv[(size_t)MV*EMBED];
__device__ float g_k   [(size_t)ML*EMBED];
__device__ float g_vall[(size_t)ML*EMBED];
__device__ float g_S   [(size_t)BH*NV*NL];
__device__ float g_ov  [(size_t)MV*EMBED];
__device__ float g_ol  [(size_t)ML*EMBED];
__device__ float g_colm[BH*NL];
__device__ float g_cols[BH*NL];
__device__ float g_pm  [32*BH*NL];
__device__ float g_ps  [32*BH*NL];
__device__ float g_Wt  [5505024];
__device__ __align__(16) uint32_t g_qs[(size_t)BH*NV*64];
__device__ __align__(16) uint32_t g_ks[(size_t)BH*NL*64];

#define WT_V2Q   0
#define WT_L2K   1048576
#define WT_V2V   1835008
#define WT_L2V   2883584
#define WT_V2OUT 3670016
#define WT_L2OUT 4718592

// ---------------- fused weight transposes ----------------
struct TP6 { const float* W[6]; float* Wt[6]; int K[6]; int N[6]; };
__global__ void transpose6(TP6 tp)
{
    __shared__ float t[32][33];
    const int id = blockIdx.z;
    const int K = tp.K[id], N = tp.N[id];
    const int kb = blockIdx.y * 32, nb = blockIdx.x * 32;
    if (kb >= K || nb >= N) return;
    const float* W = tp.W[id];
    float* Wt = tp.Wt[id];
    const int x = threadIdx.x, y = threadIdx.y;
    #pragma unroll
    for (int i = 0; i < 32; i += 8)
        t[y + i][x] = W[(size_t)(kb + y + i) * N + nb + x];
    __syncthreads();
    #pragma unroll
    for (int i = 0; i < 32; i += 8)
        Wt[(size_t)(nb + y + i) * K + kb + x] = t[x][y + i];
}

// ---------------- helpers ----------------
__device__ __forceinline__ float tf32_rn(float x) {
    uint32_t r; asm("cvt.rna.tf32.f32 %0, %1;" : "=r"(r) : "f"(x));
    return __uint_as_float(r);
}
__device__ __forceinline__ void mma_tf32(float* c, const uint32_t* a, const uint32_t* b) {
    asm volatile("mma.sync.aligned.m16n8k8.row.col.f32.tf32.tf32.f32 "
        "{%0,%1,%2,%3}, {%4,%5,%6,%7}, {%8,%9}, {%0,%1,%2,%3};"
        : "+f"(c[0]), "+f"(c[1]), "+f"(c[2]), "+f"(c[3])
        : "r"(a[0]), "r"(a[1]), "r"(a[2]), "r"(a[3]), "r"(b[0]), "r"(b[1]));
}
__device__ __forceinline__ void mma_bf16(float* c, const uint32_t* a, uint32_t b0, uint32_t b1) {
    asm volatile("mma.sync.aligned.m16n8k16.row.col.f32.bf16.bf16.f32 "
        "{%0,%1,%2,%3}, {%4,%5,%6,%7}, {%8,%9}, {%0,%1,%2,%3};"
        : "+f"(c[0]), "+f"(c[1]), "+f"(c[2]), "+f"(c[3])
        : "r"(a[0]), "r"(a[1]), "r"(a[2]), "r"(a[3]), "r"(b0), "r"(b1));
}
__device__ __forceinline__ uint32_t pack_bf(float even, float odd) {
    uint32_t r; asm("cvt.rn.bf16x2.f32 %0, %1, %2;" : "=r"(r) : "f"(odd), "f"(even));
    return r;
}
#define HI_EVEN(u) __uint_as_float((u) << 16)
#define HI_ODD(u)  __uint_as_float((u) & 0xffff0000u)

// ---------------- split fp32 -> bf16 hi/lo packed planes (pairs along d) ----------------
__global__ void split_pack(const float* __restrict__ src, uint32_t* __restrict__ dst,
                           int rowsPerPlane, int rpShift)
{
    int idx = blockIdx.x * 256 + threadIdx.x;
    int quad = idx & 7;
    int R = idx >> 3;
    int p = R >> rpShift;
    int q = R & (rowsPerPlane - 1);
    int b = p >> 4, h = p & 15;
    const float* s = src + ((size_t)(b * rowsPerPlane + q)) * EMBED + h * 64 + quad * 8;
    float4 x0 = *(const float4*)s;
    float4 x1 = *(const float4*)(s + 4);
    uint32_t hi[4], lo[4];
    float e[8] = { x0.x, x0.y, x0.z, x0.w, x1.x, x1.y, x1.z, x1.w };
    #pragma unroll
    for (int i = 0; i < 4; i++) {
        hi[i] = pack_bf(e[2*i], e[2*i+1]);
        lo[i] = pack_bf(e[2*i] - HI_EVEN(hi[i]), e[2*i+1] - HI_ODD(hi[i]));
    }
    uint32_t* d = dst + (size_t)R * 64;
    *(uint4*)(d + quad * 4)      = *(uint4*)hi;
    *(uint4*)(d + 32 + quad * 4) = *(uint4*)lo;
}

// ---------------- tf32 mma.sync GEMM (projections) ----------------
#define ASTR   36
#define TBUF   (128*ASTR)
__global__ __launch_bounds__(256, 1) void mma_gemm(
    const float* __restrict__ A, const float* __restrict__ Bt,
    const float* __restrict__ bias, float* __restrict__ C,
    int M, int N, int K)
{
    extern __shared__ float smf[];
    float* As = smf;
    float* Bs = smf + 2 * TBUF;
    __shared__ float sbias[128];
    const int tid = threadIdx.x, w = tid >> 5, lane = tid & 31;
    const int grp = lane >> 2, tg = lane & 3;
    const int wm = (w & 1) * 64, wn = (w >> 1) * 32;
    const int m0 = blockIdx.y * 128, n0 = blockIdx.x * 128;
    if (tid < 128) sbias[tid] = bias[n0 + tid];
    const float* Ab = A + (size_t)m0 * K;
    const float* Bb = Bt + (size_t)n0 * K;
    const int ldr = tid >> 3, ldc = (tid & 7) * 4;
    float acc[4][4][4];
    #pragma unroll
    for (int i = 0; i < 4; i++)
        #pragma unroll
        for (int j = 0; j < 4; j++)
            #pragma unroll
            for (int t = 0; t < 4; t++) acc[i][j][t] = 0.f;
    const int NC = K / 32;
    #pragma unroll
    for (int i = 0; i < 4; i++) {
        int r = i * 32 + ldr;
        float4 va = *(const float4*)(Ab + (size_t)r * K + ldc);
        float4 vb = *(const float4*)(Bb + (size_t)r * K + ldc);
        float* da = As + r * ASTR + ldc;
        float* db = Bs + r * ASTR + ldc;
        da[0]=tf32_rn(va.x); da[1]=tf32_rn(va.y); da[2]=tf32_rn(va.z); da[3]=tf32_rn(va.w);
        db[0]=tf32_rn(vb.x); db[1]=tf32_rn(vb.y); db[2]=tf32_rn(vb.z); db[3]=tf32_rn(vb.w);
    }
    __syncthreads();
    for (int c = 0; c < NC; c++) {
        const int b = c & 1;
        float4 pa[4], pb[4];
        if (c + 1 < NC) {
            const int k0 = (c + 1) * 32;
            #pragma unroll
            for (int i = 0; i < 4; i++) {
                int r = i * 32 + ldr;
                pa[i] = *(const float4*)(Ab + (size_t)r * K + k0 + ldc);
                pb[i] = *(const float4*)(Bb + (size_t)r * K + k0 + ldc);
            }
        }
        const float* Ac = As + b * TBUF;
        const float* Bc = Bs + b * TBUF;
        #pragma unroll
        for (int k0 = 0; k0 < 32; k0 += 8) {
            uint32_t af[4][4], bf[4][2];
            #pragma unroll
            for (int i = 0; i < 4; i++) {
                int row = wm + i * 16 + grp;
                af[i][0] = __float_as_uint(Ac[row * ASTR + k0 + tg]);
                af[i][1] = __float_as_uint(Ac[(row + 8) * ASTR + k0 + tg]);
                af[i][2] = __float_as_uint(Ac[row * ASTR + k0 + tg + 4]);
                af[i][3] = __float_as_uint(Ac[(row + 8) * ASTR + k0 + tg + 4]);
            }
            #pragma unroll
            for (int j = 0; j < 4; j++) {
                int n = wn + j * 8 + grp;
                bf[j][0] = __float_as_uint(Bc[n * ASTR + k0 + tg]);
                bf[j][1] = __float_as_uint(Bc[n * ASTR + k0 + tg + 4]);
            }
            #pragma unroll
            for (int i = 0; i < 4; i++)
                #pragma unroll
                for (int j = 0; j < 4; j++)
                    mma_tf32(acc[i][j], af[i], bf[j]);
        }
        if (c + 1 < NC) {
            __syncthreads();
            const int nb = 1 - b;
            float* da0 = As + nb * TBUF;
            float* db0 = Bs + nb * TBUF;
            #pragma unroll
            for (int i = 0; i < 4; i++) {
                int r = i * 32 + ldr;
                float* da = da0 + r * ASTR + ldc;
                float* db = db0 + r * ASTR + ldc;
                da[0]=tf32_rn(pa[i].x); da[1]=tf32_rn(pa[i].y); da[2]=tf32_rn(pa[i].z); da[3]=tf32_rn(pa[i].w);
                db[0]=tf32_rn(pb[i].x); db[1]=tf32_rn(pb[i].y); db[2]=tf32_rn(pb[i].z); db[3]=tf32_rn(pb[i].w);
            }
            __syncthreads();
        }
    }
    #pragma unroll
    for (int i = 0; i < 4; i++) {
        int r0 = m0 + wm + i * 16 + grp;
        float* C0 = C + (size_t)r0 * N + n0;
        float* C1 = C + (size_t)(r0 + 8) * N + n0;
        #pragma unroll
        for (int j = 0; j < 4; j++) {
            int cc = wn + j * 8 + 2 * tg;
            float2 v0 = { acc[i][j][0] + sbias[cc], acc[i][j][1] + sbias[cc + 1] };
            float2 v1 = { acc[i][j][2] + sbias[cc], acc[i][j][3] + sbias[cc + 1] };
            *(float2*)(C0 + cc) = v0;
            *(float2*)(C1 + cc) = v1;
        }
    }
}
#define GEMM_SMEM (4 * TBUF * sizeof(float))

// ---------------- scores via bf16x3 mma + fused col-stat partials ----------------
#define SSTR 68
#define SC_SMEM (2*128*SSTR*4 + 4*128*4)
__global__ __launch_bounds__(256, 1) void scores_mma()
{
    extern __shared__ uint32_t su[];
    uint32_t* As = su;
    uint32_t* Bs = su + 128 * SSTR;
    float* red = (float*)(su + 2 * 128 * SSTR);
    const int tid = threadIdx.x, w = tid >> 5, lane = tid & 31;
    const int grp = lane >> 2, tg = lane & 3;
    const int wq = w >> 1, wk = w & 1;
    const int p = blockIdx.z;
    const int q0 = blockIdx.y * 128, k0 = blockIdx.x * 128;

    const uint4* sa = (const uint4*)(g_qs + ((size_t)p * NV + q0) * 64);
    const uint4* sb = (const uint4*)(g_ks + ((size_t)p * NL + k0) * 64);
    #pragma unroll
    for (int i = 0; i < 8; i++) {
        int L = i * 256 + tid;
        int r = L >> 4, c = L & 15;
        *(uint4*)(As + r * SSTR + c * 4) = sa[r * 16 + c];
        *(uint4*)(Bs + r * SSTR + c * 4) = sb[r * 16 + c];
    }
    __syncthreads();

    float acc[2][8][4];
    #pragma unroll
    for (int i = 0; i < 2; i++)
        #pragma unroll
        for (int j = 0; j < 8; j++)
            #pragma unroll
            for (int t = 0; t < 4; t++) acc[i][j][t] = 0.f;

    #pragma unroll
    for (int s = 0; s < 12; s++) {
        const int seg = s >> 2, ss = (s & 3) * 8;
        const int ab = (seg == 2) ? 32 + ss : ss;
        const int bb = (seg == 1) ? 32 + ss : ss;
        uint32_t a[2][4], bf[8][2];
        #pragma unroll
        for (int i = 0; i < 2; i++) {
            int row = wq * 32 + i * 16 + grp;
            a[i][0] = As[row * SSTR + ab + tg];
            a[i][1] = As[(row + 8) * SSTR + ab + tg];
            a[i][2] = As[row * SSTR + ab + 4 + tg];
            a[i][3] = As[(row + 8) * SSTR + ab + 4 + tg];
        }
        #pragma unroll
        for (int j = 0; j < 8; j++) {
            int n = wk * 64 + j * 8 + grp;
            bf[j][0] = Bs[n * SSTR + bb + tg];
            bf[j][1] = Bs[n * SSTR + bb + 4 + tg];
        }
        #pragma unroll
        for (int i = 0; i < 2; i++)
            #pragma unroll
            for (int j = 0; j < 8; j++)
                mma_bf16(acc[i][j], a[i], bf[j][0], bf[j][1]);
    }

    #pragma unroll
    for (int i = 0; i < 2; i++)
        #pragma unroll
        for (int j = 0; j < 8; j++)
            #pragma unroll
            for (int t = 0; t < 4; t++) acc[i][j][t] *= 0.25f;

    #pragma unroll
    for (int i = 0; i < 2; i++)
        #pragma unroll
        for (int h2 = 0; h2 < 2; h2++) {
            int rq = q0 + wq * 32 + i * 16 + grp + h2 * 8;
            float* Sr = g_S + ((size_t)p * NV + rq) * NL + k0 + wk * 64;
            #pragma unroll
            for (int j = 0; j < 8; j++) {
                float2 v = { acc[i][j][h2 * 2], acc[i][j][h2 * 2 + 1] };
                *(float2*)(Sr + j * 8 + 2 * tg) = v;
            }
        }

    float cm[8][2];
    #pragma unroll
    for (int j = 0; j < 8; j++)
        #pragma unroll
        for (int par = 0; par < 2; par++) {
            float m = fmaxf(fmaxf(acc[0][j][par], acc[0][j][2 + par]),
                            fmaxf(acc[1][j][par], acc[1][j][2 + par]));
            #pragma unroll
            for (int o = 4; o <= 16; o <<= 1) m = fmaxf(m, __shfl_xor_sync(0xffffffffu, m, o));
            cm[j][par] = m;
        }
    if (grp == 0)
        #pragma unroll
        for (int j = 0; j < 8; j++)
            #pragma unroll
            for (int par = 0; par < 2; par++)
                red[wq * 128 + wk * 64 + j * 8 + 2 * tg + par] = cm[j][par];
    __syncthreads();
    float tmreg = 0.f;
    if (tid < 128)
        tmreg = fmaxf(fmaxf(red[tid], red[128 + tid]), fmaxf(red[256 + tid], red[384 + tid]));
    __syncthreads();
    if (tid < 128) red[tid] = tmreg;
    __syncthreads();
    float tmv[8][2];
    #pragma unroll
    for (int j = 0; j < 8; j++)
        #pragma unroll
        for (int par = 0; par < 2; par++)
            tmv[j][par] = red[wk * 64 + j * 8 + 2 * tg + par];
    __syncthreads();
    #pragma unroll
    for (int j = 0; j < 8; j++)
        #pragma unroll
        for (int par = 0; par < 2; par++) {
            float s = __expf(acc[0][j][par] - tmv[j][par]) + __expf(acc[0][j][2 + par] - tmv[j][par])
                    + __expf(acc[1][j][par] - tmv[j][par]) + __expf(acc[1][j][2 + par] - tmv[j][par]);
            #pragma unroll
            for (int o = 4; o <= 16; o <<= 1) s += __shfl_xor_sync(0xffffffffu, s, o);
            cm[j][par] = s;
        }
    if (grp == 0)
        #pragma unroll
        for (int j = 0; j < 8; j++)
            #pragma unroll
            for (int par = 0; par < 2; par++)
                red[wq * 128 + wk * 64 + j * 8 + 2 * tg + par] = cm[j][par];
    __syncthreads();
    if (tid < 128) {
        float s = red[tid] + red[128 + tid] + red[256 + tid] + red[384 + tid];
        size_t o = ((size_t)blockIdx.y * BH + p) * NL + k0 + tid;
        g_pm[o] = tmreg;
        g_ps[o] = s;
    }
}

// ---------------- combine 32 qtile partials -> colm/cols ----------------
__global__ void colcombine()
{
    const int p = blockIdx.x, col = threadIdx.x;
    float m = -3.0e38f;
    #pragma unroll 8
    for (int t = 0; t < 32; t++)
        m = fmaxf(m, g_pm[((size_t)t * BH + p) * NL + col]);
    float s = 0.f;
    #pragma unroll 8
    for (int t = 0; t < 32; t++) {
        size_t o = ((size_t)t * BH + p) * NL + col;
        s += __expf(g_pm[o] - m) * g_ps[o];
    }
    g_colm[p * NL + col] = m;
    g_cols[p * NL + col] = s;
}

// ---------------- out_v via bf16x3 mma: row softmax (masked) + P @ Vl ----------------
#define OV_VH 0
#define OV_VL (128*72)
#define OV_MB (2*128*72)
#define OV_ST (OV_MB + 256)
#define OVM_SMEM ((OV_ST + 8*32) * 4)
__global__ __launch_bounds__(256, 1) void out_v_mma(const int* __restrict__ mask)
{
    extern __shared__ uint32_t su[];
    float* smf = (float*)su;
    const int bh = blockIdx.y, b = bh >> 4, h = bh & 15;
    const int q0 = blockIdx.x * 128;
    const int tid = threadIdx.x, w = tid >> 5, lane = tid & 31;
    const int grp = lane >> 2, tg = lane & 3;

    smf[OV_MB + tid] = (mask[b * NL + tid] == 0) ? -1.0e9f : 0.0f;
    #pragma unroll
    for (int i = 0; i < 8; i++) {
        int idx = i * 256 + tid;
        int kp = idx >> 4, dg = (idx & 15) * 4;
        const float* v0 = &g_vall[((size_t)(b * NL + 2 * kp)) * EMBED + h * 64 + dg];
        float4 A = *(const float4*)v0;
        float4 B = *(const float4*)(v0 + EMBED);
        float av[4] = { A.x, A.y, A.z, A.w }, bv[4] = { B.x, B.y, B.z, B.w };
        #pragma unroll
        for (int d = 0; d < 4; d++) {
            uint32_t hi = pack_bf(av[d], bv[d]);
            uint32_t lo = pack_bf(av[d] - HI_EVEN(hi), bv[d] - HI_ODD(hi));
            su[OV_VH + kp * 72 + dg + d] = hi;
            su[OV_VL + kp * 72 + dg + d] = lo;
        }
    }
    __syncthreads();

    for (int r = 0; r < 16; r++) {
        const float* Sr = g_S + ((size_t)bh * NV + q0 + w * 16 + r) * NL;
        float4 s1 = *(const float4*)(Sr + lane * 8);
        float4 s2 = *(const float4*)(Sr + lane * 8 + 4);
        float4 m1 = *(const float4*)&smf[OV_MB + lane * 8];
        float4 m2 = *(const float4*)&smf[OV_MB + lane * 8 + 4];
        float x[8] = { s1.x+m1.x, s1.y+m1.y, s1.z+m1.z, s1.w+m1.w,
                       s2.x+m2.x, s2.y+m2.y, s2.z+m2.z, s2.w+m2.w };
        float m = x[0];
        #pragma unroll
        for (int j = 1; j < 8; j++) m = fmaxf(m, x[j]);
        #pragma unroll
        for (int o = 16; o > 0; o >>= 1) m = fmaxf(m, __shfl_xor_sync(0xffffffffu, m, o));
        float s = 0.f;
        #pragma unroll
        for (int j = 0; j < 8; j++) s += __expf(x[j] - m);
        #pragma unroll
        for (int o = 16; o > 0; o >>= 1) s += __shfl_xor_sync(0xffffffffu, s, o);
        if (lane == 0) { smf[OV_ST + w * 32 + r] = m; smf[OV_ST + w * 32 + 16 + r] = 1.0f / s; }
    }
    __syncwarp();

    const float ma = smf[OV_ST + w * 32 + grp],     ia = smf[OV_ST + w * 32 + 16 + grp];
    const float mb2 = smf[OV_ST + w * 32 + grp + 8], ib = smf[OV_ST + w * 32 + 24 + grp];
    const float* Sa = g_S + ((size_t)bh * NV + q0 + w * 16 + grp) * NL;
    const float* Sb = Sa + 8 * NL;

    float acc[8][4];
    #pragma unroll
    for (int j = 0; j < 8; j++)
        #pragma unroll
        for (int t = 0; t < 4; t++) acc[j][t] = 0.f;

    for (int c = 0; c < 16; c++) {
        const int ka = c * 16 + 2 * tg, kb = ka + 8;
        float2 mba = *(const float2*)&smf[OV_MB + ka];
        float2 mbb = *(const float2*)&smf[OV_MB + kb];
        float2 s00 = *(const float2*)(Sa + ka), s01 = *(const float2*)(Sa + kb);
        float2 s10 = *(const float2*)(Sb + ka), s11 = *(const float2*)(Sb + kb);
        float e0 = __expf(s00.x + mba.x - ma) * ia, e1 = __expf(s00.y + mba.y - ma) * ia;
        float e2 = __expf(s10.x + mba.x - mb2) * ib, e3 = __expf(s10.y + mba.y - mb2) * ib;
        float e4 = __expf(s01.x + mbb.x - ma) * ia, e5 = __expf(s01.y + mbb.y - ma) * ia;
        float e6 = __expf(s11.x + mbb.x - mb2) * ib, e7 = __expf(s11.y + mbb.y - mb2) * ib;
        uint32_t ah[4], al[4];
        ah[0] = pack_bf(e0, e1); al[0] = pack_bf(e0 - HI_EVEN(ah[0]), e1 - HI_ODD(ah[0]));
        ah[1] = pack_bf(e2, e3); al[1] = pack_bf(e2 - HI_EVEN(ah[1]), e3 - HI_ODD(ah[1]));
        ah[2] = pack_bf(e4, e5); al[2] = pack_bf(e4 - HI_EVEN(ah[2]), e5 - HI_ODD(ah[2]));
        ah[3] = pack_bf(e6, e7); al[3] = pack_bf(e6 - HI_EVEN(ah[3]), e7 - HI_ODD(ah[3]));
        #pragma unroll
        for (int j = 0; j < 8; j++) {
            uint32_t bh0 = su[OV_VH + (c * 8 + tg) * 72 + j * 8 + grp];
            uint32_t bh1 = su[OV_VH + (c * 8 + 4 + tg) * 72 + j * 8 + grp];
            uint32_t bl0 = su[OV_VL + (c * 8 + tg) * 72 + j * 8 + grp];
            uint32_t bl1 = su[OV_VL + (c * 8 + 4 + tg) * 72 + j * 8 + grp];
            mma_bf16(acc[j], ah, bh0, bh1);
            mma_bf16(acc[j], ah, bl0, bl1);
            mma_bf16(acc[j], al, bh0, bh1);
        }
    }
    const int rowa = b * NV + q0 + w * 16 + grp;
    #pragma unroll
    for (int j = 0; j < 8; j++) {
        float2 v0 = { acc[j][0], acc[j][1] };
        float2 v1 = { acc[j][2], acc[j][3] };
        *(float2*)&g_ov[(size_t)rowa * EMBED + h * 64 + j * 8 + 2 * tg] = v0;
        *(float2*)&g_ov[(size_t)(rowa + 8) * EMBED + h * 64 + j * 8 + 2 * tg] = v1;
    }
}

// ---------------- out_l via bf16x3 mma: P^T @ Vv (column softmax, unmasked) ----------------
#define OL_VH 0
#define OL_VL (32*72)
#define OL_SF (2*32*72)
#define OL_CM (OL_SF + 64*132)
#define OL_CI (OL_CM + 128)
#define OLM_SMEM ((OL_CI + 128) * 4)
__global__ __launch_bounds__(256, 1) void out_l_mma()
{
    extern __shared__ uint32_t su[];
    float* smf = (float*)su;
    const int bh = blockIdx.y, b = bh >> 4, h = bh & 15;
    const int k0g = blockIdx.x * 128;
    const int tid = threadIdx.x, w = tid >> 5, lane = tid & 31;
    const int grp = lane >> 2, tg = lane & 3;

    if (tid < 128) {
        smf[OL_CM + tid] = g_colm[bh * NL + k0g + tid];
        smf[OL_CI + tid] = 1.0f / g_cols[bh * NL + k0g + tid];
    }

    float acc[8][4];
    #pragma unroll
    for (int j = 0; j < 8; j++)
        #pragma unroll
        for (int t = 0; t < 4; t++) acc[j][t] = 0.f;

    for (int qc = 0; qc < NV; qc += 64) {
        __syncthreads();
        #pragma unroll
        for (int pss = 0; pss < 8; pss++) {
            int row = pss * 8 + (tid >> 5);
            int col4 = (tid & 31) * 4;
            *(float4*)&smf[OL_SF + row * 132 + col4] =
                *(const float4*)&g_S[((size_t)bh * NV + qc + row) * NL + k0g + col4];
        }
        #pragma unroll
        for (int pss = 0; pss < 2; pss++) {
            int idx = pss * 256 + tid;
            int qp = idx >> 4, dg = (idx & 15) * 4;
            const float* v0 = &g_valv[((size_t)(b * NV + qc + 2 * qp)) * EMBED + h * 64 + dg];
            float4 A = *(const float4*)v0;
            float4 B = *(const float4*)(v0 + EMBED);
            float av[4] = { A.x, A.y, A.z, A.w }, bv[4] = { B.x, B.y, B.z, B.w };
            #pragma unroll
            for (int d = 0; d < 4; d++) {
                uint32_t hi = pack_bf(av[d], bv[d]);
                uint32_t lo = pack_bf(av[d] - HI_EVEN(hi), bv[d] - HI_ODD(hi));
                su[OL_VH + qp * 72 + dg + d] = hi;
                su[OL_VL + qp * 72 + dg + d] = lo;
            }
        }
        __syncthreads();

        const int ka = w * 16 + grp, kb = ka + 8;
        const float cma = smf[OL_CM + ka], cia = smf[OL_CI + ka];
        const float cmb = smf[OL_CM + kb], cib = smf[OL_CI + kb];
        #pragma unroll
        for (int qs = 0; qs < 4; qs++) {
            const int qa = qs * 16 + 2 * tg;
            float x00 = smf[OL_SF + qa * 132 + ka],       x01 = smf[OL_SF + (qa + 1) * 132 + ka];
            float x10 = smf[OL_SF + qa * 132 + kb],       x11 = smf[OL_SF + (qa + 1) * 132 + kb];
            float x20 = smf[OL_SF + (qa + 8) * 132 + ka], x21 = smf[OL_SF + (qa + 9) * 132 + ka];
            float x30 = smf[OL_SF + (qa + 8) * 132 + kb], x31 = smf[OL_SF + (qa + 9) * 132 + kb];
            float e0 = __expf(x00 - cma) * cia, e1 = __expf(x01 - cma) * cia;
            float e2 = __expf(x10 - cmb) * cib, e3 = __expf(x11 - cmb) * cib;
            float e4 = __expf(x20 - cma) * cia, e5 = __expf(x21 - cma) * cia;
            float e6 = __expf(x30 - cmb) * cib, e7 = __expf(x31 - cmb) * cib;
            uint32_t ah[4], al[4];
            ah[0] = pack_bf(e0, e1); al[0] = pack_bf(e0 - HI_EVEN(ah[0]), e1 - HI_ODD(ah[0]));
            ah[1] = pack_bf(e2, e3); al[1] = pack_bf(e2 - HI_EVEN(ah[1]), e3 - HI_ODD(ah[1]));
            ah[2] = pack_bf(e4, e5); al[2] = pack_bf(e4 - HI_EVEN(ah[2]), e5 - HI_ODD(ah[2]));
            ah[3] = pack_bf(e6, e7); al[3] = pack_bf(e6 - HI_EVEN(ah[3]), e7 - HI_ODD(ah[3]));
            #pragma unroll
            for (int j = 0; j < 8; j++) {
                uint32_t bh0 = su[OL_VH + (qs * 8 + tg) * 72 + j * 8 + grp];
                uint32_t bh1 = su[OL_VH + (qs * 8 + 4 + tg) * 72 + j * 8 + grp];
                uint32_t bl0 = su[OL_VL + (qs * 8 + tg) * 72 + j * 8 + grp];
                uint32_t bl1 = su[OL_VL + (qs * 8 + 4 + tg) * 72 + j * 8 + grp];
                mma_bf16(acc[j], ah, bh0, bh1);
                mma_bf16(acc[j], ah, bl0, bl1);
                mma_bf16(acc[j], al, bh0, bh1);
            }
        }
    }
    const int krow = b * NL + k0g + w * 16 + grp;
    #pragma unroll
    for (int j = 0; j < 8; j++) {
        float2 v0 = { acc[j][0], acc[j][1] };
        float2 v1 = { acc[j][2], acc[j][3] };
        *(float2*)&g_ol[(size_t)krow * EMBED + h * 64 + j * 8 + 2 * tg] = v0;
        *(float2*)&g_ol[(size_t)(krow + 8) * EMBED + h * 64 + j * 8 + 2 * tg] = v1;
    }
}

// ---------------- host launcher ----------------
extern "C" void kernel_launch(void* const* d_in, const int* in_sizes, int n_in,
                              void* d_out, int out_size)
{
    (void)in_sizes; (void)n_in; (void)out_size;
    const float* v       = (const float*)d_in[0];
    const float* l       = (const float*)d_in[1];
    const int*   mask    = (const int*)  d_in[2];
    const float* W_v2q   = (const float*)d_in[3];
    const float* b_v2q   = (const float*)d_in[4];
    const float* W_l2k   = (const float*)d_in[5];
    const float* b_l2k   = (const float*)d_in[6];
    const float* W_v2v   = (const float*)d_in[7];
    const float* b_v2v   = (const float*)d_in[8];
    const float* W_l2v   = (const float*)d_in[9];
    const float* b_l2v   = (const float*)d_in[10];
    const float* W_v2out = (const float*)d_in[11];
    const float* b_v2out = (const float*)d_in[12];
    const float* W_l2out = (const float*)d_in[13];
    const float* b_l2out = (const float*)d_in[14];
    float* out = (float*)d_out;

    float *p_q, *p_valv, *p_k, *p_vall, *p_ov, *p_ol, *p_wt;
    uint32_t *p_qs, *p_ks;
    cudaGetSymbolAddress((void**)&p_q,    g_q);
    cudaGetSymbolAddress((void**)&p_valv, g_valv);
    cudaGetSymbolAddress((void**)&p_k,    g_k);
    cudaGetSymbolAddress((void**)&p_vall, g_vall);
    cudaGetSymbolAddress((void**)&p_ov,   g_ov);
    cudaGetSymbolAddress((void**)&p_ol,   g_ol);
    cudaGetSymbolAddress((void**)&p_wt,   g_Wt);
    cudaGetSymbolAddress((void**)&p_qs,   g_qs);
    cudaGetSymbolAddress((void**)&p_ks,   g_ks);

    static int attr_set = 0;
    if (!attr_set) {
        cudaFuncSetAttribute(mma_gemm,   cudaFuncAttributeMaxDynamicSharedMemorySize, GEMM_SMEM);
        cudaFuncSetAttribute(scores_mma, cudaFuncAttributeMaxDynamicSharedMemorySize, SC_SMEM);
        cudaFuncSetAttribute(out_v_mma,  cudaFuncAttributeMaxDynamicSharedMemorySize, OVM_SMEM);
        cudaFuncSetAttribute(out_l_mma,  cudaFuncAttributeMaxDynamicSharedMemorySize, OLM_SMEM);
        attr_set = 1;
    }

    TP6 tp;
    tp.W[0]=W_v2q;  tp.Wt[0]=p_wt+WT_V2Q;   tp.K[0]=EMBED; tp.N[0]=EMBED;
    tp.W[1]=W_l2k;  tp.Wt[1]=p_wt+WT_L2K;   tp.K[1]=LDIM;  tp.N[1]=EMBED;
    tp.W[2]=W_v2v;  tp.Wt[2]=p_wt+WT_V2V;   tp.K[2]=EMBED; tp.N[2]=EMBED;
    tp.W[3]=W_l2v;  tp.Wt[3]=p_wt+WT_L2V;   tp.K[3]=LDIM;  tp.N[3]=EMBED;
    tp.W[4]=W_v2out;tp.Wt[4]=p_wt+WT_V2OUT; tp.K[4]=EMBED; tp.N[4]=EMBED;
    tp.W[5]=W_l2out;tp.Wt[5]=p_wt+WT_L2OUT; tp.K[5]=EMBED; tp.N[5]=LDIM;
    transpose6<<<dim3(32, 32, 6), dim3(32, 8)>>>(tp);

    mma_gemm<<<dim3(EMBED/128, ML/128), 256, GEMM_SMEM>>>(l, p_wt+WT_L2K, b_l2k, p_k,    ML, EMBED, LDIM);
    mma_gemm<<<dim3(EMBED/128, ML/128), 256, GEMM_SMEM>>>(l, p_wt+WT_L2V, b_l2v, p_vall, ML, EMBED, LDIM);
    // big vision GEMMs at launch idx 3-4 (idx 3 = ncu profile window)
    mma_gemm<<<dim3(EMBED/128, MV/128), 256, GEMM_SMEM>>>(v, p_wt+WT_V2Q, b_v2q, p_q,    MV, EMBED, EMBED);
    mma_gemm<<<dim3(EMBED/128, MV/128), 256, GEMM_SMEM>>>(v, p_wt+WT_V2V, b_v2v, p_valv, MV, EMBED, EMBED);
    split_pack<<<(BH*NL*8)/256, 256>>>(p_k, p_ks, NL, 8);
    split_pack<<<(BH*NV*8)/256, 256>>>(p_q, p_qs, NV, 12);
    scores_mma<<<dim3(NL/128, NV/128, BH), 256, SC_SMEM>>>();
    colcombine<<<BH, NL>>>();
    out_v_mma<<<dim3(NV/128, BH), 256, OVM_SMEM>>>(mask);
    out_l_mma<<<dim3(NL/128, BH), 256, OLM_SMEM>>>();
    mma_gemm<<<dim3(EMBED/128, MV/128), 256, GEMM_SMEM>>>(p_ov, p_wt+WT_V2OUT, b_v2out, out, MV, EMBED, EMBED);
    mma_gemm<<<dim3(LDIM/128,  ML/128), 256, GEMM_SMEM>>>(p_ol, p_wt+WT_L2OUT, b_l2out, out + (size_t)MV*EMBED, ML, LDIM, EMBED);
}

// round 9
// speedup vs baseline: 3.5496x; 1.7905x over previous
#include <cuda_runtime.h>
#include <cuda_bf16.h>
#include <cstdint>
#include <cstddef>

#define BATCH   4
#define NV      4096
#define NL      256
#define EMBED   1024
#define HEADS   16
#define HDIM    64
#define LDIM    768
#define BH      (BATCH*HEADS)
#define MV      (BATCH*NV)
#define ML      (BATCH*NL)

// ---------------- scratch ----------------
__device__ float g_q   [(size_t)MV*EMBED];
__device__ float g_valv[(size_t)MV*EMBED];
__device__ float g_k   [(size_t)ML*EMBED];
__device__ float g_vall[(size_t)ML*EMBED];
__device__ float g_S   [(size_t)BH*NV*NL];
__device__ float g_ov  [(size_t)MV*EMBED];   // also: tf32-rounded v staging
__device__ float g_ol  [(size_t)ML*EMBED];   // also: tf32-rounded l staging
__device__ float g_colm[BH*NL];
__device__ float g_cols[BH*NL];
__device__ float g_pm  [32*BH*NL];
__device__ float g_ps  [32*BH*NL];
__device__ float g_Wt  [5505024];
__device__ __align__(16) uint32_t g_qs[(size_t)BH*NV*64];
__device__ __align__(16) uint32_t g_ks[(size_t)BH*NL*64];

#define WT_V2Q   0
#define WT_L2K   1048576
#define WT_V2V   1835008
#define WT_L2V   2883584
#define WT_V2OUT 3670016
#define WT_L2OUT 4718592

// ---------------- helpers ----------------
__device__ __forceinline__ float tf32_rn(float x) {
    uint32_t r; asm("cvt.rna.tf32.f32 %0, %1;" : "=r"(r) : "f"(x));
    return __uint_as_float(r);
}
__device__ __forceinline__ void mma_tf32(float* c, const uint32_t* a, const uint32_t* b) {
    asm volatile("mma.sync.aligned.m16n8k8.row.col.f32.tf32.tf32.f32 "
        "{%0,%1,%2,%3}, {%4,%5,%6,%7}, {%8,%9}, {%0,%1,%2,%3};"
        : "+f"(c[0]), "+f"(c[1]), "+f"(c[2]), "+f"(c[3])
        : "r"(a[0]), "r"(a[1]), "r"(a[2]), "r"(a[3]), "r"(b[0]), "r"(b[1]));
}
__device__ __forceinline__ void mma_bf16(float* c, const uint32_t* a, uint32_t b0, uint32_t b1) {
    asm volatile("mma.sync.aligned.m16n8k16.row.col.f32.bf16.bf16.f32 "
        "{%0,%1,%2,%3}, {%4,%5,%6,%7}, {%8,%9}, {%0,%1,%2,%3};"
        : "+f"(c[0]), "+f"(c[1]), "+f"(c[2]), "+f"(c[3])
        : "r"(a[0]), "r"(a[1]), "r"(a[2]), "r"(a[3]), "r"(b0), "r"(b1));
}
__device__ __forceinline__ uint32_t pack_bf(float even, float odd) {
    uint32_t r; asm("cvt.rn.bf16x2.f32 %0, %1, %2;" : "=r"(r) : "f"(odd), "f"(even));
    return r;
}
#define HI_EVEN(u) __uint_as_float((u) << 16)
#define HI_ODD(u)  __uint_as_float((u) & 0xffff0000u)

__device__ __forceinline__ uint32_t smem_u32(const void* p) {
    uint32_t a;
    asm("{ .reg .u64 t; cvta.to.shared.u64 t, %1; cvt.u32.u64 %0, t; }" : "=r"(a) : "l"(p));
    return a;
}
__device__ __forceinline__ void ldsm4(uint32_t* r, uint32_t a) {
    asm volatile("ldmatrix.sync.aligned.m8n8.x4.shared.b16 {%0,%1,%2,%3}, [%4];"
        : "=r"(r[0]), "=r"(r[1]), "=r"(r[2]), "=r"(r[3]) : "r"(a));
}
__device__ __forceinline__ void cp16(uint32_t dst, const void* src) {
    asm volatile("cp.async.cg.shared.global [%0], [%1], 16;" :: "r"(dst), "l"(src));
}
#define CP_COMMIT() asm volatile("cp.async.commit_group;" ::: "memory")
#define CP_WAIT(n)  asm volatile("cp.async.wait_group %0;" :: "n"(n) : "memory")

// ---------------- fused weight transposes (emit tf32-rounded) ----------------
struct TP6 { const float* W[6]; float* Wt[6]; int K[6]; int N[6]; };
__global__ void transpose6(TP6 tp)
{
    __shared__ float t[32][33];
    const int id = blockIdx.z;
    const int K = tp.K[id], N = tp.N[id];
    const int kb = blockIdx.y * 32, nb = blockIdx.x * 32;
    if (kb >= K || nb >= N) return;
    const float* W = tp.W[id];
    float* Wt = tp.Wt[id];
    const int x = threadIdx.x, y = threadIdx.y;
    #pragma unroll
    for (int i = 0; i < 32; i += 8)
        t[y + i][x] = W[(size_t)(kb + y + i) * N + nb + x];
    __syncthreads();
    #pragma unroll
    for (int i = 0; i < 32; i += 8)
        Wt[(size_t)(nb + y + i) * K + kb + x] = tf32_rn(t[x][y + i]);
}

// ---------------- elementwise tf32 rounding ----------------
__global__ void round_tf32(const float* __restrict__ src, float* __restrict__ dst)
{
    int i = blockIdx.x * 256 + threadIdx.x;
    float4 x = ((const float4*)src)[i];
    x.x = tf32_rn(x.x); x.y = tf32_rn(x.y); x.z = tf32_rn(x.z); x.w = tf32_rn(x.w);
    ((float4*)dst)[i] = x;
}

// ---------------- split fp32 -> bf16 hi/lo packed planes ----------------
__global__ void split_pack(const float* __restrict__ src, uint32_t* __restrict__ dst,
                           int rowsPerPlane, int rpShift)
{
    int idx = blockIdx.x * 256 + threadIdx.x;
    int quad = idx & 7;
    int R = idx >> 3;
    int p = R >> rpShift;
    int q = R & (rowsPerPlane - 1);
    int b = p >> 4, h = p & 15;
    const float* s = src + ((size_t)(b * rowsPerPlane + q)) * EMBED + h * 64 + quad * 8;
    float4 x0 = *(const float4*)s;
    float4 x1 = *(const float4*)(s + 4);
    uint32_t hi[4], lo[4];
    float e[8] = { x0.x, x0.y, x0.z, x0.w, x1.x, x1.y, x1.z, x1.w };
    #pragma unroll
    for (int i = 0; i < 4; i++) {
        hi[i] = pack_bf(e[2*i], e[2*i+1]);
        lo[i] = pack_bf(e[2*i] - HI_EVEN(hi[i]), e[2*i+1] - HI_ODD(hi[i]));
    }
    uint32_t* d = dst + (size_t)R * 64;
    *(uint4*)(d + quad * 4)      = *(uint4*)hi;
    *(uint4*)(d + 32 + quad * 4) = *(uint4*)lo;
}

// ---------------- tf32 mma.sync GEMM v2: cp.async + ldmatrix, 2 CTAs/SM ----------------
// Inputs MUST be pre-rounded to tf32. C = A[M,K] @ Bt[N,K]^T + bias.
#define ASTR   36
#define TBUF   (128*ASTR)              // floats per operand per stage
#define TBUFB  (TBUF*4)                // bytes
__global__ __launch_bounds__(256, 2) void mma_gemm(
    const float* __restrict__ A, const float* __restrict__ Bt,
    const float* __restrict__ bias, float* __restrict__ C,
    int M, int N, int K)
{
    extern __shared__ float smf[];
    __shared__ float sbias[128];
    const int tid = threadIdx.x, w = tid >> 5, lane = tid & 31;
    const int grp = lane >> 2, tg = lane & 3;
    const int wm = (w & 1) * 64, wn = (w >> 1) * 32;
    const int m0 = blockIdx.y * 128, n0 = blockIdx.x * 128;
    if (tid < 128) sbias[tid] = bias[n0 + tid];

    const float* Ab = A + (size_t)m0 * K;
    const float* Bb = Bt + (size_t)n0 * K;
    const int ldr = tid >> 3, ldc = (tid & 7) * 4;

    const uint32_t uA = smem_u32(smf);
    const uint32_t uB = uA + 2 * TBUFB;

    // ldmatrix per-lane offsets
    const int arow = ((lane >> 3) & 1) * 8 + (lane & 7);
    const int acol = ((lane >> 4) & 1) * 4;
    const int brow = ((lane >> 4) & 1) * 8 + (lane & 7);
    const int bcol = ((lane >> 3) & 1) * 4;

    float acc[4][4][4];
    #pragma unroll
    for (int i = 0; i < 4; i++)
        #pragma unroll
        for (int j = 0; j < 4; j++)
            #pragma unroll
            for (int t = 0; t < 4; t++) acc[i][j][t] = 0.f;

    const int NC = K / 32;
    // prologue: async copy chunk 0 -> stage 0
    #pragma unroll
    for (int i = 0; i < 4; i++) {
        int r = i * 32 + ldr;
        cp16(uA + (r * ASTR + ldc) * 4, Ab + (size_t)r * K + ldc);
        cp16(uB + (r * ASTR + ldc) * 4, Bb + (size_t)r * K + ldc);
    }
    CP_COMMIT();

    for (int c = 0; c < NC; c++) {
        const int b = c & 1;
        if (c + 1 < NC) {
            const int nb = 1 - b;
            const int k0 = (c + 1) * 32;
            #pragma unroll
            for (int i = 0; i < 4; i++) {
                int r = i * 32 + ldr;
                cp16(uA + nb * TBUFB + (r * ASTR + ldc) * 4, Ab + (size_t)r * K + k0 + ldc);
                cp16(uB + nb * TBUFB + (r * ASTR + ldc) * 4, Bb + (size_t)r * K + k0 + ldc);
            }
            CP_COMMIT();
            CP_WAIT(1);
        } else {
            CP_WAIT(0);
        }
        __syncthreads();

        const uint32_t uAc = uA + b * TBUFB;
        const uint32_t uBc = uB + b * TBUFB;
        #pragma unroll
        for (int s = 0; s < 4; s++) {
            const int k0 = s * 8;
            uint32_t af[4][4], bfr[8];
            #pragma unroll
            for (int i = 0; i < 4; i++)
                ldsm4(af[i], uAc + (((wm + i * 16 + arow) * ASTR) + k0 + acol) * 4);
            #pragma unroll
            for (int jj = 0; jj < 2; jj++)
                ldsm4(&bfr[jj * 4], uBc + (((wn + jj * 16 + brow) * ASTR) + k0 + bcol) * 4);
            #pragma unroll
            for (int i = 0; i < 4; i++)
                #pragma unroll
                for (int j = 0; j < 4; j++)
                    mma_tf32(acc[i][j], af[i], &bfr[j * 2]);
        }
        __syncthreads();
    }

    #pragma unroll
    for (int i = 0; i < 4; i++) {
        int r0 = m0 + wm + i * 16 + grp;
        float* C0 = C + (size_t)r0 * N + n0;
        float* C1 = C + (size_t)(r0 + 8) * N + n0;
        #pragma unroll
        for (int j = 0; j < 4; j++) {
            int cc = wn + j * 8 + 2 * tg;
            float2 v0 = { acc[i][j][0] + sbias[cc], acc[i][j][1] + sbias[cc + 1] };
            float2 v1 = { acc[i][j][2] + sbias[cc], acc[i][j][3] + sbias[cc + 1] };
            *(float2*)(C0 + cc) = v0;
            *(float2*)(C1 + cc) = v1;
        }
    }
}
#define GEMM_SMEM (4 * TBUF * sizeof(float))

// ---------------- scores via bf16x3 mma + fused col-stat partials ----------------
#define SSTR 68
#define SC_SMEM (2*128*SSTR*4 + 4*128*4)
__global__ __launch_bounds__(256, 1) void scores_mma()
{
    extern __shared__ uint32_t su[];
    uint32_t* As = su;
    uint32_t* Bs = su + 128 * SSTR;
    float* red = (float*)(su + 2 * 128 * SSTR);
    const int tid = threadIdx.x, w = tid >> 5, lane = tid & 31;
    const int grp = lane >> 2, tg = lane & 3;
    const int wq = w >> 1, wk = w & 1;
    const int p = blockIdx.z;
    const int q0 = blockIdx.y * 128, k0 = blockIdx.x * 128;

    const uint4* sa = (const uint4*)(g_qs + ((size_t)p * NV + q0) * 64);
    const uint4* sb = (const uint4*)(g_ks + ((size_t)p * NL + k0) * 64);
    #pragma unroll
    for (int i = 0; i < 8; i++) {
        int L = i * 256 + tid;
        int r = L >> 4, c = L & 15;
        *(uint4*)(As + r * SSTR + c * 4) = sa[r * 16 + c];
        *(uint4*)(Bs + r * SSTR + c * 4) = sb[r * 16 + c];
    }
    __syncthreads();

    float acc[2][8][4];
    #pragma unroll
    for (int i = 0; i < 2; i++)
        #pragma unroll
        for (int j = 0; j < 8; j++)
            #pragma unroll
            for (int t = 0; t < 4; t++) acc[i][j][t] = 0.f;

    #pragma unroll
    for (int s = 0; s < 12; s++) {
        const int seg = s >> 2, ss = (s & 3) * 8;
        const int ab = (seg == 2) ? 32 + ss : ss;
        const int bb = (seg == 1) ? 32 + ss : ss;
        uint32_t a[2][4], bf[8][2];
        #pragma unroll
        for (int i = 0; i < 2; i++) {
            int row = wq * 32 + i * 16 + grp;
            a[i][0] = As[row * SSTR + ab + tg];
            a[i][1] = As[(row + 8) * SSTR + ab + tg];
            a[i][2] = As[row * SSTR + ab + 4 + tg];
            a[i][3] = As[(row + 8) * SSTR + ab + 4 + tg];
        }
        #pragma unroll
        for (int j = 0; j < 8; j++) {
            int n = wk * 64 + j * 8 + grp;
            bf[j][0] = Bs[n * SSTR + bb + tg];
            bf[j][1] = Bs[n * SSTR + bb + 4 + tg];
        }
        #pragma unroll
        for (int i = 0; i < 2; i++)
            #pragma unroll
            for (int j = 0; j < 8; j++)
                mma_bf16(acc[i][j], a[i], bf[j][0], bf[j][1]);
    }

    #pragma unroll
    for (int i = 0; i < 2; i++)
        #pragma unroll
        for (int j = 0; j < 8; j++)
            #pragma unroll
            for (int t = 0; t < 4; t++) acc[i][j][t] *= 0.25f;

    #pragma unroll
    for (int i = 0; i < 2; i++)
        #pragma unroll
        for (int h2 = 0; h2 < 2; h2++) {
            int rq = q0 + wq * 32 + i * 16 + grp + h2 * 8;
            float* Sr = g_S + ((size_t)p * NV + rq) * NL + k0 + wk * 64;
            #pragma unroll
            for (int j = 0; j < 8; j++) {
                float2 v = { acc[i][j][h2 * 2], acc[i][j][h2 * 2 + 1] };
                *(float2*)(Sr + j * 8 + 2 * tg) = v;
            }
        }

    float cm[8][2];
    #pragma unroll
    for (int j = 0; j < 8; j++)
        #pragma unroll
        for (int par = 0; par < 2; par++) {
            float m = fmaxf(fmaxf(acc[0][j][par], acc[0][j][2 + par]),
                            fmaxf(acc[1][j][par], acc[1][j][2 + par]));
            #pragma unroll
            for (int o = 4; o <= 16; o <<= 1) m = fmaxf(m, __shfl_xor_sync(0xffffffffu, m, o));
            cm[j][par] = m;
        }
    if (grp == 0)
        #pragma unroll
        for (int j = 0; j < 8; j++)
            #pragma unroll
            for (int par = 0; par < 2; par++)
                red[wq * 128 + wk * 64 + j * 8 + 2 * tg + par] = cm[j][par];
    __syncthreads();
    float tmreg = 0.f;
    if (tid < 128)
        tmreg = fmaxf(fmaxf(red[tid], red[128 + tid]), fmaxf(red[256 + tid], red[384 + tid]));
    __syncthreads();
    if (tid < 128) red[tid] = tmreg;
    __syncthreads();
    float tmv[8][2];
    #pragma unroll
    for (int j = 0; j < 8; j++)
        #pragma unroll
        for (int par = 0; par < 2; par++)
            tmv[j][par] = red[wk * 64 + j * 8 + 2 * tg + par];
    __syncthreads();
    #pragma unroll
    for (int j = 0; j < 8; j++)
        #pragma unroll
        for (int par = 0; par < 2; par++) {
            float s = __expf(acc[0][j][par] - tmv[j][par]) + __expf(acc[0][j][2 + par] - tmv[j][par])
                    + __expf(acc[1][j][par] - tmv[j][par]) + __expf(acc[1][j][2 + par] - tmv[j][par]);
            #pragma unroll
            for (int o = 4; o <= 16; o <<= 1) s += __shfl_xor_sync(0xffffffffu, s, o);
            cm[j][par] = s;
        }
    if (grp == 0)
        #pragma unroll
        for (int j = 0; j < 8; j++)
            #pragma unroll
            for (int par = 0; par < 2; par++)
                red[wq * 128 + wk * 64 + j * 8 + 2 * tg + par] = cm[j][par];
    __syncthreads();
    if (tid < 128) {
        float s = red[tid] + red[128 + tid] + red[256 + tid] + red[384 + tid];
        size_t o = ((size_t)blockIdx.y * BH + p) * NL + k0 + tid;
        g_pm[o] = tmreg;
        g_ps[o] = s;
    }
}

// ---------------- combine partials ----------------
__global__ void colcombine()
{
    const int p = blockIdx.x, col = threadIdx.x;
    float m = -3.0e38f;
    #pragma unroll 8
    for (int t = 0; t < 32; t++)
        m = fmaxf(m, g_pm[((size_t)t * BH + p) * NL + col]);
    float s = 0.f;
    #pragma unroll 8
    for (int t = 0; t < 32; t++) {
        size_t o = ((size_t)t * BH + p) * NL + col;
        s += __expf(g_pm[o] - m) * g_ps[o];
    }
    g_colm[p * NL + col] = m;
    g_cols[p * NL + col] = s;
}

// ---------------- out_v via bf16x3 mma (emit tf32-rounded) ----------------
#define OV_VH 0
#define OV_VL (128*72)
#define OV_MB (2*128*72)
#define OV_ST (OV_MB + 256)
#define OVM_SMEM ((OV_ST + 8*32) * 4)
__global__ __launch_bounds__(256, 1) void out_v_mma(const int* __restrict__ mask)
{
    extern __shared__ uint32_t su[];
    float* smf = (float*)su;
    const int bh = blockIdx.y, b = bh >> 4, h = bh & 15;
    const int q0 = blockIdx.x * 128;
    const int tid = threadIdx.x, w = tid >> 5, lane = tid & 31;
    const int grp = lane >> 2, tg = lane & 3;

    smf[OV_MB + tid] = (mask[b * NL + tid] == 0) ? -1.0e9f : 0.0f;
    #pragma unroll
    for (int i = 0; i < 8; i++) {
        int idx = i * 256 + tid;
        int kp = idx >> 4, dg = (idx & 15) * 4;
        const float* v0 = &g_vall[((size_t)(b * NL + 2 * kp)) * EMBED + h * 64 + dg];
        float4 A = *(const float4*)v0;
        float4 B = *(const float4*)(v0 + EMBED);
        float av[4] = { A.x, A.y, A.z, A.w }, bv[4] = { B.x, B.y, B.z, B.w };
        #pragma unroll
        for (int d = 0; d < 4; d++) {
            uint32_t hi = pack_bf(av[d], bv[d]);
            uint32_t lo = pack_bf(av[d] - HI_EVEN(hi), bv[d] - HI_ODD(hi));
            su[OV_VH + kp * 72 + dg + d] = hi;
            su[OV_VL + kp * 72 + dg + d] = lo;
        }
    }
    __syncthreads();

    for (int r = 0; r < 16; r++) {
        const float* Sr = g_S + ((size_t)bh * NV + q0 + w * 16 + r) * NL;
        float4 s1 = *(const float4*)(Sr + lane * 8);
        float4 s2 = *(const float4*)(Sr + lane * 8 + 4);
        float4 m1 = *(const float4*)&smf[OV_MB + lane * 8];
        float4 m2 = *(const float4*)&smf[OV_MB + lane * 8 + 4];
        float x[8] = { s1.x+m1.x, s1.y+m1.y, s1.z+m1.z, s1.w+m1.w,
                       s2.x+m2.x, s2.y+m2.y, s2.z+m2.z, s2.w+m2.w };
        float m = x[0];
        #pragma unroll
        for (int j = 1; j < 8; j++) m = fmaxf(m, x[j]);
        #pragma unroll
        for (int o = 16; o > 0; o >>= 1) m = fmaxf(m, __shfl_xor_sync(0xffffffffu, m, o));
        float s = 0.f;
        #pragma unroll
        for (int j = 0; j < 8; j++) s += __expf(x[j] - m);
        #pragma unroll
        for (int o = 16; o > 0; o >>= 1) s += __shfl_xor_sync(0xffffffffu, s, o);
        if (lane == 0) { smf[OV_ST + w * 32 + r] = m; smf[OV_ST + w * 32 + 16 + r] = 1.0f / s; }
    }
    __syncwarp();

    const float ma = smf[OV_ST + w * 32 + grp],     ia = smf[OV_ST + w * 32 + 16 + grp];
    const float mb2 = smf[OV_ST + w * 32 + grp + 8], ib = smf[OV_ST + w * 32 + 24 + grp];
    const float* Sa = g_S + ((size_t)bh * NV + q0 + w * 16 + grp) * NL;
    const float* Sb = Sa + 8 * NL;

    float acc[8][4];
    #pragma unroll
    for (int j = 0; j < 8; j++)
        #pragma unroll
        for (int t = 0; t < 4; t++) acc[j][t] = 0.f;

    for (int c = 0; c < 16; c++) {
        const int ka = c * 16 + 2 * tg, kb = ka + 8;
        float2 mba = *(const float2*)&smf[OV_MB + ka];
        float2 mbb = *(const float2*)&smf[OV_MB + kb];
        float2 s00 = *(const float2*)(Sa + ka), s01 = *(const float2*)(Sa + kb);
        float2 s10 = *(const float2*)(Sb + ka), s11 = *(const float2*)(Sb + kb);
        float e0 = __expf(s00.x + mba.x - ma) * ia, e1 = __expf(s00.y + mba.y - ma) * ia;
        float e2 = __expf(s10.x + mba.x - mb2) * ib, e3 = __expf(s10.y + mba.y - mb2) * ib;
        float e4 = __expf(s01.x + mbb.x - ma) * ia, e5 = __expf(s01.y + mbb.y - ma) * ia;
        float e6 = __expf(s11.x + mbb.x - mb2) * ib, e7 = __expf(s11.y + mbb.y - mb2) * ib;
        uint32_t ah[4], al[4];
        ah[0] = pack_bf(e0, e1); al[0] = pack_bf(e0 - HI_EVEN(ah[0]), e1 - HI_ODD(ah[0]));
        ah[1] = pack_bf(e2, e3); al[1] = pack_bf(e2 - HI_EVEN(ah[1]), e3 - HI_ODD(ah[1]));
        ah[2] = pack_bf(e4, e5); al[2] = pack_bf(e4 - HI_EVEN(ah[2]), e5 - HI_ODD(ah[2]));
        ah[3] = pack_bf(e6, e7); al[3] = pack_bf(e6 - HI_EVEN(ah[3]), e7 - HI_ODD(ah[3]));
        #pragma unroll
        for (int j = 0; j < 8; j++) {
            uint32_t bh0 = su[OV_VH + (c * 8 + tg) * 72 + j * 8 + grp];
            uint32_t bh1 = su[OV_VH + (c * 8 + 4 + tg) * 72 + j * 8 + grp];
            uint32_t bl0 = su[OV_VL + (c * 8 + tg) * 72 + j * 8 + grp];
            uint32_t bl1 = su[OV_VL + (c * 8 + 4 + tg) * 72 + j * 8 + grp];
            mma_bf16(acc[j], ah, bh0, bh1);
            mma_bf16(acc[j], ah, bl0, bl1);
            mma_bf16(acc[j], al, bh0, bh1);
        }
    }
    const int rowa = b * NV + q0 + w * 16 + grp;
    #pragma unroll
    for (int j = 0; j < 8; j++) {
        float2 v0 = { tf32_rn(acc[j][0]), tf32_rn(acc[j][1]) };
        float2 v1 = { tf32_rn(acc[j][2]), tf32_rn(acc[j][3]) };
        *(float2*)&g_ov[(size_t)rowa * EMBED + h * 64 + j * 8 + 2 * tg] = v0;
        *(float2*)&g_ov[(size_t)(rowa + 8) * EMBED + h * 64 + j * 8 + 2 * tg] = v1;
    }
}

// ---------------- out_l via bf16x3 mma (emit tf32-rounded) ----------------
#define OL_VH 0
#define OL_VL (32*72)
#define OL_SF (2*32*72)
#define OL_CM (OL_SF + 64*132)
#define OL_CI (OL_CM + 128)
#define OLM_SMEM ((OL_CI + 128) * 4)
__global__ __launch_bounds__(256, 1) void out_l_mma()
{
    extern __shared__ uint32_t su[];
    float* smf = (float*)su;
    const int bh = blockIdx.y, b = bh >> 4, h = bh & 15;
    const int k0g = blockIdx.x * 128;
    const int tid = threadIdx.x, w = tid >> 5, lane = tid & 31;
    const int grp = lane >> 2, tg = lane & 3;

    if (tid < 128) {
        smf[OL_CM + tid] = g_colm[bh * NL + k0g + tid];
        smf[OL_CI + tid] = 1.0f / g_cols[bh * NL + k0g + tid];
    }

    float acc[8][4];
    #pragma unroll
    for (int j = 0; j < 8; j++)
        #pragma unroll
        for (int t = 0; t < 4; t++) acc[j][t] = 0.f;

    for (int qc = 0; qc < NV; qc += 64) {
        __syncthreads();
        #pragma unroll
        for (int pss = 0; pss < 8; pss++) {
            int row = pss * 8 + (tid >> 5);
            int col4 = (tid & 31) * 4;
            *(float4*)&smf[OL_SF + row * 132 + col4] =
                *(const float4*)&g_S[((size_t)bh * NV + qc + row) * NL + k0g + col4];
        }
        #pragma unroll
        for (int pss = 0; pss < 2; pss++) {
            int idx = pss * 256 + tid;
            int qp = idx >> 4, dg = (idx & 15) * 4;
            const float* v0 = &g_valv[((size_t)(b * NV + qc + 2 * qp)) * EMBED + h * 64 + dg];
            float4 A = *(const float4*)v0;
            float4 B = *(const float4*)(v0 + EMBED);
            float av[4] = { A.x, A.y, A.z, A.w }, bv[4] = { B.x, B.y, B.z, B.w };
            #pragma unroll
            for (int d = 0; d < 4; d++) {
                uint32_t hi = pack_bf(av[d], bv[d]);
                uint32_t lo = pack_bf(av[d] - HI_EVEN(hi), bv[d] - HI_ODD(hi));
                su[OL_VH + qp * 72 + dg + d] = hi;
                su[OL_VL + qp * 72 + dg + d] = lo;
            }
        }
        __syncthreads();

        const int ka = w * 16 + grp, kb = ka + 8;
        const float cma = smf[OL_CM + ka], cia = smf[OL_CI + ka];
        const float cmb = smf[OL_CM + kb], cib = smf[OL_CI + kb];
        #pragma unroll
        for (int qs = 0; qs < 4; qs++) {
            const int qa = qs * 16 + 2 * tg;
            float x00 = smf[OL_SF + qa * 132 + ka],       x01 = smf[OL_SF + (qa + 1) * 132 + ka];
            float x10 = smf[OL_SF + qa * 132 + kb],       x11 = smf[OL_SF + (qa + 1) * 132 + kb];
            float x20 = smf[OL_SF + (qa + 8) * 132 + ka], x21 = smf[OL_SF + (qa + 9) * 132 + ka];
            float x30 = smf[OL_SF + (qa + 8) * 132 + kb], x31 = smf[OL_SF + (qa + 9) * 132 + kb];
            float e0 = __expf(x00 - cma) * cia, e1 = __expf(x01 - cma) * cia;
            float e2 = __expf(x10 - cmb) * cib, e3 = __expf(x11 - cmb) * cib;
            float e4 = __expf(x20 - cma) * cia, e5 = __expf(x21 - cma) * cia;
            float e6 = __expf(x30 - cmb) * cib, e7 = __expf(x31 - cmb) * cib;
            uint32_t ah[4], al[4];
            ah[0] = pack_bf(e0, e1); al[0] = pack_bf(e0 - HI_EVEN(ah[0]), e1 - HI_ODD(ah[0]));
            ah[1] = pack_bf(e2, e3); al[1] = pack_bf(e2 - HI_EVEN(ah[1]), e3 - HI_ODD(ah[1]));
            ah[2] = pack_bf(e4, e5); al[2] = pack_bf(e4 - HI_EVEN(ah[2]), e5 - HI_ODD(ah[2]));
            ah[3] = pack_bf(e6, e7); al[3] = pack_bf(e6 - HI_EVEN(ah[3]), e7 - HI_ODD(ah[3]));
            #pragma unroll
            for (int j = 0; j < 8; j++) {
                uint32_t bh0 = su[OL_VH + (qs * 8 + tg) * 72 + j * 8 + grp];
                uint32_t bh1 = su[OL_VH + (qs * 8 + 4 + tg) * 72 + j * 8 + grp];
                uint32_t bl0 = su[OL_VL + (qs * 8 + tg) * 72 + j * 8 + grp];
                uint32_t bl1 = su[OL_VL + (qs * 8 + 4 + tg) * 72 + j * 8 + grp];
                mma_bf16(acc[j], ah, bh0, bh1);
                mma_bf16(acc[j], ah, bl0, bl1);
                mma_bf16(acc[j], al, bh0, bh1);
            }
        }
    }
    const int krow = b * NL + k0g + w * 16 + grp;
    #pragma unroll
    for (int j = 0; j < 8; j++) {
        float2 v0 = { tf32_rn(acc[j][0]), tf32_rn(acc[j][1]) };
        float2 v1 = { tf32_rn(acc[j][2]), tf32_rn(acc[j][3]) };
        *(float2*)&g_ol[(size_t)krow * EMBED + h * 64 + j * 8 + 2 * tg] = v0;
        *(float2*)&g_ol[(size_t)(krow + 8) * EMBED + h * 64 + j * 8 + 2 * tg] = v1;
    }
}

// ---------------- host launcher ----------------
extern "C" void kernel_launch(void* const* d_in, const int* in_sizes, int n_in,
                              void* d_out, int out_size)
{
    (void)in_sizes; (void)n_in; (void)out_size;
    const float* v       = (const float*)d_in[0];
    const float* l       = (const float*)d_in[1];
    const int*   mask    = (const int*)  d_in[2];
    const float* W_v2q   = (const float*)d_in[3];
    const float* b_v2q   = (const float*)d_in[4];
    const float* W_l2k   = (const float*)d_in[5];
    const float* b_l2k   = (const float*)d_in[6];
    const float* W_v2v   = (const float*)d_in[7];
    const float* b_v2v   = (const float*)d_in[8];
    const float* W_l2v   = (const float*)d_in[9];
    const float* b_l2v   = (const float*)d_in[10];
    const float* W_v2out = (const float*)d_in[11];
    const float* b_v2out = (const float*)d_in[12];
    const float* W_l2out = (const float*)d_in[13];
    const float* b_l2out = (const float*)d_in[14];
    float* out = (float*)d_out;

    float *p_q, *p_valv, *p_k, *p_vall, *p_ov, *p_ol, *p_wt;
    uint32_t *p_qs, *p_ks;
    cudaGetSymbolAddress((void**)&p_q,    g_q);
    cudaGetSymbolAddress((void**)&p_valv, g_valv);
    cudaGetSymbolAddress((void**)&p_k,    g_k);
    cudaGetSymbolAddress((void**)&p_vall, g_vall);
    cudaGetSymbolAddress((void**)&p_ov,   g_ov);
    cudaGetSymbolAddress((void**)&p_ol,   g_ol);
    cudaGetSymbolAddress((void**)&p_wt,   g_Wt);
    cudaGetSymbolAddress((void**)&p_qs,   g_qs);
    cudaGetSymbolAddress((void**)&p_ks,   g_ks);

    static int attr_set = 0;
    if (!attr_set) {
        cudaFuncSetAttribute(mma_gemm,   cudaFuncAttributeMaxDynamicSharedMemorySize, GEMM_SMEM);
        cudaFuncSetAttribute(scores_mma, cudaFuncAttributeMaxDynamicSharedMemorySize, SC_SMEM);
        cudaFuncSetAttribute(out_v_mma,  cudaFuncAttributeMaxDynamicSharedMemorySize, OVM_SMEM);
        cudaFuncSetAttribute(out_l_mma,  cudaFuncAttributeMaxDynamicSharedMemorySize, OLM_SMEM);
        attr_set = 1;
    }

    TP6 tp;
    tp.W[0]=W_v2q;  tp.Wt[0]=p_wt+WT_V2Q;   tp.K[0]=EMBED; tp.N[0]=EMBED;
    tp.W[1]=W_l2k;  tp.Wt[1]=p_wt+WT_L2K;   tp.K[1]=LDIM;  tp.N[1]=EMBED;
    tp.W[2]=W_v2v;  tp.Wt[2]=p_wt+WT_V2V;   tp.K[2]=EMBED; tp.N[2]=EMBED;
    tp.W[3]=W_l2v;  tp.Wt[3]=p_wt+WT_L2V;   tp.K[3]=LDIM;  tp.N[3]=EMBED;
    tp.W[4]=W_v2out;tp.Wt[4]=p_wt+WT_V2OUT; tp.K[4]=EMBED; tp.N[4]=EMBED;
    tp.W[5]=W_l2out;tp.Wt[5]=p_wt+WT_L2OUT; tp.K[5]=EMBED; tp.N[5]=LDIM;
    // 0: transposes (+tf32 round); 1-2: round inputs into staging (g_ov <- v, g_ol <- l)
    transpose6<<<dim3(32, 32, 6), dim3(32, 8)>>>(tp);
    round_tf32<<<(MV * EMBED / 4) / 256, 256>>>(v, p_ov);
    round_tf32<<<(ML * LDIM  / 4) / 256, 256>>>(l, p_ol);

    // 3: big vision GEMM (ncu profile window) ... 4-6
    mma_gemm<<<dim3(EMBED/128, MV/128), 256, GEMM_SMEM>>>(p_ov, p_wt+WT_V2Q, b_v2q, p_q,    MV, EMBED, EMBED);
    mma_gemm<<<dim3(EMBED/128, MV/128), 256, GEMM_SMEM>>>(p_ov, p_wt+WT_V2V, b_v2v, p_valv, MV, EMBED, EMBED);
    mma_gemm<<<dim3(EMBED/128, ML/128), 256, GEMM_SMEM>>>(p_ol, p_wt+WT_L2K, b_l2k, p_k,    ML, EMBED, LDIM);
    mma_gemm<<<dim3(EMBED/128, ML/128), 256, GEMM_SMEM>>>(p_ol, p_wt+WT_L2V, b_l2v, p_vall, ML, EMBED, LDIM);

    split_pack<<<(BH*NL*8)/256, 256>>>(p_k, p_ks, NL, 8);
    split_pack<<<(BH*NV*8)/256, 256>>>(p_q, p_qs, NV, 12);
    scores_mma<<<dim3(NL/128, NV/128, BH), 256, SC_SMEM>>>();
    colcombine<<<BH, NL>>>();
    out_v_mma<<<dim3(NV/128, BH), 256, OVM_SMEM>>>(mask);
    out_l_mma<<<dim3(NL/128, BH), 256, OLM_SMEM>>>();
    mma_gemm<<<dim3(EMBED/128, MV/128), 256, GEMM_SMEM>>>(p_ov, p_wt+WT_V2OUT, b_v2out, out, MV, EMBED, EMBED);
    mma_gemm<<<dim3(LDIM/128,  ML/128), 256, GEMM_SMEM>>>(p_ol, p_wt+WT_L2OUT, b_l2out, out + (size_t)MV*EMBED, ML, LDIM, EMBED);
}